// round 13
// baseline (speedup 1.0000x reference)
#include <cuda_runtime.h>
#include <cuda_bf16.h>
#include <cstdint>
#include <math.h>

#define NN 8192
#define HD 1024
#define EE 8192

// ---------------- scratch (device globals; allocation-free) ----------------
__device__ __nv_bfloat16 g_Abf[(size_t)NN * NN];   // 128 MB
__device__ __nv_bfloat16 g_W1bf[(size_t)HD * NN];  // 16 MB
__device__ __nv_bfloat16 g_W2bf[(size_t)NN * HD];  // 16 MB
__device__ __nv_bfloat16 g_H1bf[(size_t)NN * HD];  // 16 MB
__device__ __nv_bfloat16 g_H2bf[(size_t)NN * NN];  // 128 MB
__device__ float g_d2sq[NN];
__device__ float g_acc[3];
__device__ unsigned char g_mask[NN];

// ---------------- PTX helpers ----------------
__device__ __forceinline__ uint32_t smem_u32(const void* p) {
    uint32_t a;
    asm("{ .reg .u64 t; cvta.to.shared.u64 t, %1; cvt.u32.u64 %0, t; }" : "=r"(a) : "l"(p));
    return a;
}

#define CP_ASYNC16(dst, src) \
    asm volatile("cp.async.cg.shared.global [%0], [%1], 16;" :: "r"(dst), "l"(src) : "memory")
#define CP_COMMIT() asm volatile("cp.async.commit_group;" ::: "memory")
template <int N>
__device__ __forceinline__ void cp_wait() {
    asm volatile("cp.async.wait_group %0;" :: "n"(N) : "memory");
}

__device__ __forceinline__ void ldsm4(uint32_t* r, uint32_t addr) {
    asm volatile("ldmatrix.sync.aligned.m8n8.x4.shared.b16 {%0,%1,%2,%3}, [%4];"
                 : "=r"(r[0]), "=r"(r[1]), "=r"(r[2]), "=r"(r[3]) : "r"(addr));
}

__device__ __forceinline__ void mma_bf16(float* c, const uint32_t* a,
                                         uint32_t b0, uint32_t b1) {
    asm volatile(
        "mma.sync.aligned.m16n8k16.row.col.f32.bf16.bf16.f32 "
        "{%0,%1,%2,%3}, {%4,%5,%6,%7}, {%8,%9}, {%0,%1,%2,%3};"
        : "+f"(c[0]), "+f"(c[1]), "+f"(c[2]), "+f"(c[3])
        : "r"(a[0]), "r"(a[1]), "r"(a[2]), "r"(a[3]), "r"(b0), "r"(b1));
}

__device__ __forceinline__ uint32_t sw128(uint32_t off) {
    return off ^ ((off >> 3) & 0x70);
}

// shared stage loader: A tile 128x64 bf16 + B tile 128x64 bf16, SW128 swizzled
__device__ __forceinline__ void load_stage(
    const __nv_bfloat16* __restrict__ Abf, const __nv_bfloat16* __restrict__ Bbf,
    int K, int bm0, int bn0, int kt, uint32_t stageBase, int tid)
{
#pragma unroll
    for (int r = 0; r < 4; r++) {
        int idx = tid + r * 256;
        int row = idx >> 3, ck = idx & 7;
        uint32_t sw = sw128((uint32_t)(row * 128 + ck * 16));
        const void* srcA = (const char*)(Abf + (size_t)(bm0 + row) * K + kt) + ck * 16;
        CP_ASYNC16(stageBase + sw, srcA);
        const void* srcB = (const char*)(Bbf + (size_t)(bn0 + row) * K + kt) + ck * 16;
        CP_ASYNC16(stageBase + 16384 + sw, srcB);
    }
    CP_COMMIT();
}

#define STAGE_BYTES 32768
#define G_SMEM (3 * STAGE_BYTES)      // 96 KB: 3 stages; x2 CTAs = 192 KB/SM

// =======================================================================
// GEMM1: 3-stage pipeline, 96KB smem, 2 CTAs/SM
// =======================================================================
__global__ void __launch_bounds__(256, 2)
gemm1_hmma(const __nv_bfloat16* __restrict__ Abf,
           const __nv_bfloat16* __restrict__ Bbf,
           const float* __restrict__ bias,
           __nv_bfloat16* __restrict__ Hout,
           int K, int Nc)
{
    extern __shared__ __align__(1024) char smem[];
    const uint32_t sb0 = smem_u32(smem);
    const int tid = threadIdx.x;
    const int wid = tid >> 5, lid = tid & 31;
    const int warp_m = wid >> 2;
    const int warp_n = wid & 3;
    const int bm0 = blockIdx.y * 128;
    const int bn0 = blockIdx.x * 128;

    const int q  = lid >> 3;
    const int r8 = lid & 7;
    const int arowb = warp_m * 64 + (q & 1) * 8 + r8;
    const int browb = warp_n * 32 + (q & 1) * 8 + r8;
    const uint32_t kq   = (uint32_t)((q >> 1) * 16);
    const uint32_t axor = (uint32_t)((arowb & 7) << 4);
    const uint32_t bxor = (uint32_t)((browb & 7) << 4);

    float acc[4][4][4];
#pragma unroll
    for (int i = 0; i < 4; i++)
#pragma unroll
        for (int j = 0; j < 4; j++)
#pragma unroll
            for (int k = 0; k < 4; k++) acc[i][j][k] = 0.f;

    const int T = K >> 6;

    load_stage(Abf, Bbf, K, bm0, bn0, 0, sb0, tid);
    load_stage(Abf, Bbf, K, bm0, bn0, 64, sb0 + STAGE_BYTES, tid);

    for (int i = 0; i < T; i++) {
        if (i < T - 1) cp_wait<1>(); else cp_wait<0>();
        __syncthreads();
        if (i + 2 < T) {
            int pb = (i + 2) % 3;
            load_stage(Abf, Bbf, K, bm0, bn0, (i + 2) * 64,
                       sb0 + (uint32_t)pb * STAGE_BYTES, tid);
        }
        const uint32_t Ab = sb0 + (uint32_t)(i % 3) * STAGE_BYTES;
        const uint32_t Bb = Ab + 16384;

#pragma unroll
        for (int s = 0; s < 4; s++) {
            const uint32_t koff = (uint32_t)(s * 32) | kq;
            uint32_t a[4][4], bfr[2][4];
#pragma unroll
            for (int mt = 0; mt < 4; mt++)
                ldsm4(a[mt], Ab + (uint32_t)(arowb + mt * 16) * 128 + (koff ^ axor));
#pragma unroll
            for (int bt = 0; bt < 2; bt++)
                ldsm4(bfr[bt], Bb + (uint32_t)(browb + bt * 16) * 128 + (koff ^ bxor));
#pragma unroll
            for (int mt = 0; mt < 4; mt++)
#pragma unroll
                for (int nt = 0; nt < 4; nt++)
                    mma_bf16(acc[mt][nt], a[mt], bfr[nt >> 1][nt & 1], bfr[nt >> 1][(nt & 1) + 2]);
        }
        __syncthreads();
    }

    const int rr = lid >> 2;
    const int cc = (lid & 3) * 2;
#pragma unroll
    for (int nt = 0; nt < 4; nt++) {
        const int col = bn0 + warp_n * 32 + nt * 8 + cc;
        const float bb0 = bias[col], bb1 = bias[col + 1];
#pragma unroll
        for (int mt = 0; mt < 4; mt++) {
            const int row0 = bm0 + warp_m * 64 + mt * 16 + rr;
            float v0 = acc[mt][nt][0] + bb0, v1 = acc[mt][nt][1] + bb1;
            float v2 = acc[mt][nt][2] + bb0, v3 = acc[mt][nt][3] + bb1;
            float s0 = 1.f / (1.f + __expf(-v0));
            float s1 = 1.f / (1.f + __expf(-v1));
            float s2 = 1.f / (1.f + __expf(-v2));
            float s3 = 1.f / (1.f + __expf(-v3));
            __nv_bfloat162 h01 = __floats2bfloat162_rn(s0, s1);
            __nv_bfloat162 h23 = __floats2bfloat162_rn(s2, s3);
            *(uint32_t*)(Hout + (size_t)row0 * Nc + col)       = *(uint32_t*)&h01;
            *(uint32_t*)(Hout + (size_t)(row0 + 8) * Nc + col) = *(uint32_t*)&h23;
        }
    }
}

// =======================================================================
// GEMM2: 3-stage, 2 CTAs/SM, fused residual (vs bf16 A) + mask-gated stores
// =======================================================================
__global__ void __launch_bounds__(256, 2)
gemm2_fused(const __nv_bfloat16* __restrict__ Abf,
            const __nv_bfloat16* __restrict__ Bbf,
            const float* __restrict__ bias,
            __nv_bfloat16* __restrict__ Hout,
            const __nv_bfloat16* __restrict__ Aref,
            float* __restrict__ d2sq,
            const unsigned char* __restrict__ mask,
            int K, int Nc)
{
    extern __shared__ __align__(1024) char smem[];
    const uint32_t sb0 = smem_u32(smem);
    const int tid = threadIdx.x;
    const int wid = tid >> 5, lid = tid & 31;
    const int warp_m = wid >> 2;
    const int warp_n = wid & 3;
    const int bm0 = blockIdx.y * 128;
    const int bn0 = blockIdx.x * 128;

    const int q  = lid >> 3;
    const int r8 = lid & 7;
    const int arowb = warp_m * 64 + (q & 1) * 8 + r8;
    const int browb = warp_n * 32 + (q & 1) * 8 + r8;
    const uint32_t kq   = (uint32_t)((q >> 1) * 16);
    const uint32_t axor = (uint32_t)((arowb & 7) << 4);
    const uint32_t bxor = (uint32_t)((browb & 7) << 4);

    float acc[4][4][4];
#pragma unroll
    for (int i = 0; i < 4; i++)
#pragma unroll
        for (int j = 0; j < 4; j++)
#pragma unroll
            for (int k = 0; k < 4; k++) acc[i][j][k] = 0.f;

    const int T = K >> 6;   // 16

    load_stage(Abf, Bbf, K, bm0, bn0, 0, sb0, tid);
    load_stage(Abf, Bbf, K, bm0, bn0, 64, sb0 + STAGE_BYTES, tid);

    for (int i = 0; i < T; i++) {
        if (i < T - 1) cp_wait<1>(); else cp_wait<0>();
        __syncthreads();
        if (i + 2 < T) {
            int pb = (i + 2) % 3;
            load_stage(Abf, Bbf, K, bm0, bn0, (i + 2) * 64,
                       sb0 + (uint32_t)pb * STAGE_BYTES, tid);
        }
        const uint32_t Ab = sb0 + (uint32_t)(i % 3) * STAGE_BYTES;
        const uint32_t Bb = Ab + 16384;

#pragma unroll
        for (int s = 0; s < 4; s++) {
            const uint32_t koff = (uint32_t)(s * 32) | kq;
            uint32_t a[4][4], bfr[2][4];
#pragma unroll
            for (int mt = 0; mt < 4; mt++)
                ldsm4(a[mt], Ab + (uint32_t)(arowb + mt * 16) * 128 + (koff ^ axor));
#pragma unroll
            for (int bt = 0; bt < 2; bt++)
                ldsm4(bfr[bt], Bb + (uint32_t)(browb + bt * 16) * 128 + (koff ^ bxor));
#pragma unroll
            for (int mt = 0; mt < 4; mt++)
#pragma unroll
                for (int nt = 0; nt < 4; nt++)
                    mma_bf16(acc[mt][nt], a[mt], bfr[nt >> 1][nt & 1], bfr[nt >> 1][(nt & 1) + 2]);
        }
        __syncthreads();
    }

    const int rr = lid >> 2;
    const int cc = (lid & 3) * 2;
    float sum0[4] = {0.f, 0.f, 0.f, 0.f};
    float sum8[4] = {0.f, 0.f, 0.f, 0.f};
    bool m0[4], m8[4];
#pragma unroll
    for (int mt = 0; mt < 4; mt++) {
        const int row0 = bm0 + warp_m * 64 + mt * 16 + rr;
        m0[mt] = mask[row0] != 0;
        m8[mt] = mask[row0 + 8] != 0;
    }

#pragma unroll
    for (int nt = 0; nt < 4; nt++) {
        const int col = bn0 + warp_n * 32 + nt * 8 + cc;
        const float bb0 = bias[col], bb1 = bias[col + 1];
#pragma unroll
        for (int mt = 0; mt < 4; mt++) {
            const int row0 = bm0 + warp_m * 64 + mt * 16 + rr;
            float v0 = acc[mt][nt][0] + bb0, v1 = acc[mt][nt][1] + bb1;
            float v2 = acc[mt][nt][2] + bb0, v3 = acc[mt][nt][3] + bb1;
            float s0 = 1.f / (1.f + __expf(-v0));
            float s1 = 1.f / (1.f + __expf(-v1));
            float s2 = 1.f / (1.f + __expf(-v2));
            float s3 = 1.f / (1.f + __expf(-v3));
            uint32_t a01u = __ldcs((const uint32_t*)(Aref + (size_t)row0 * Nc + col));
            uint32_t a23u = __ldcs((const uint32_t*)(Aref + (size_t)(row0 + 8) * Nc + col));
            float2 a01 = __bfloat1622float2(*(const __nv_bfloat162*)&a01u);
            float2 a23 = __bfloat1622float2(*(const __nv_bfloat162*)&a23u);
            float d0 = a01.x - s0, d1 = a01.y - s1;
            float d2v = a23.x - s2, d3 = a23.y - s3;
            sum0[mt] += d0 * d0 + d1 * d1;
            sum8[mt] += d2v * d2v + d3 * d3;
            if (m0[mt]) {
                __nv_bfloat162 h01 = __floats2bfloat162_rn(s0, s1);
                __stcs((unsigned int*)(Hout + (size_t)row0 * Nc + col), *(unsigned int*)&h01);
            }
            if (m8[mt]) {
                __nv_bfloat162 h23 = __floats2bfloat162_rn(s2, s3);
                __stcs((unsigned int*)(Hout + (size_t)(row0 + 8) * Nc + col), *(unsigned int*)&h23);
            }
        }
    }

#pragma unroll
    for (int mt = 0; mt < 4; mt++) {
        float s0v = sum0[mt], s8v = sum8[mt];
        s0v += __shfl_xor_sync(0xffffffffu, s0v, 1);
        s0v += __shfl_xor_sync(0xffffffffu, s0v, 2);
        s8v += __shfl_xor_sync(0xffffffffu, s8v, 1);
        s8v += __shfl_xor_sync(0xffffffffu, s8v, 2);
        if ((lid & 3) == 0) {
            const int row0 = bm0 + warp_m * 64 + mt * 16 + rr;
            atomicAdd(&d2sq[row0], s0v);
            atomicAdd(&d2sq[row0 + 8], s8v);
        }
    }
}

// ---------------- block reduction (256 threads) ----------------
__device__ __forceinline__ float block_reduce(float v) {
    __shared__ float sh[8];
    __syncthreads();
    int lane = threadIdx.x & 31;
    int w    = threadIdx.x >> 5;
#pragma unroll
    for (int o = 16; o > 0; o >>= 1) v += __shfl_down_sync(0xffffffffu, v, o);
    if (lane == 0) sh[w] = v;
    __syncthreads();
    if (w == 0) {
        v = (lane < 8) ? sh[lane] : 0.f;
#pragma unroll
        for (int o = 4; o > 0; o >>= 1) v += __shfl_down_sync(0xffffffffu, v, o);
    }
    return v;
}

// ---------------- merged fp32 -> bf16 conversion + W row-norm fold ----------
__global__ void convert_all(const float4* __restrict__ A, uint4* __restrict__ Abf,
                            const float4* __restrict__ W1, uint4* __restrict__ W1bf,
                            const float4* __restrict__ W2, uint4* __restrict__ W2bf)
{
    const float4* in;
    uint4* out;
    int b = blockIdx.x;
    int which;
    if (b < 8192)      { in = A;  out = Abf;  which = 0; }
    else if (b < 9216) { in = W1; out = W1bf; which = 1; b -= 8192; }
    else               { in = W2; out = W2bf; which = 2; b -= 9216; }
    const int t = threadIdx.x;
    float4 v[8];
#pragma unroll
    for (int k = 0; k < 4; k++) {
        int i = b * 2048 + t * 2 + k * 512;
        v[2 * k]     = __ldcs(in + i);
        v[2 * k + 1] = __ldcs(in + i + 1);
    }
#pragma unroll
    for (int k = 0; k < 4; k++) {
        __nv_bfloat162 a0 = __floats2bfloat162_rn(v[2 * k].x,     v[2 * k].y);
        __nv_bfloat162 a1 = __floats2bfloat162_rn(v[2 * k].z,     v[2 * k].w);
        __nv_bfloat162 a2 = __floats2bfloat162_rn(v[2 * k + 1].x, v[2 * k + 1].y);
        __nv_bfloat162 a3 = __floats2bfloat162_rn(v[2 * k + 1].z, v[2 * k + 1].w);
        __stcs(out + b * 1024 + t + k * 256,
               make_uint4(*(uint32_t*)&a0, *(uint32_t*)&a1,
                          *(uint32_t*)&a2, *(uint32_t*)&a3));
    }

    if (which == 1) {
        float s = 0.f;
#pragma unroll
        for (int k = 0; k < 8; k++)
            s += v[k].x * v[k].x + v[k].y * v[k].y + v[k].z * v[k].z + v[k].w * v[k].w;
        s = block_reduce(s);
        if (t == 0) atomicAdd(&g_acc[2], sqrtf(s));
    } else if (which == 2) {
        __shared__ float srow[8];
        if (t < 8) srow[t] = 0.f;
        __syncthreads();
#pragma unroll
        for (int k = 0; k < 4; k++) {
            float p = v[2 * k].x * v[2 * k].x + v[2 * k].y * v[2 * k].y
                    + v[2 * k].z * v[2 * k].z + v[2 * k].w * v[2 * k].w
                    + v[2 * k + 1].x * v[2 * k + 1].x + v[2 * k + 1].y * v[2 * k + 1].y
                    + v[2 * k + 1].z * v[2 * k + 1].z + v[2 * k + 1].w * v[2 * k + 1].w;
#pragma unroll
            for (int o = 16; o > 0; o >>= 1) p += __shfl_xor_sync(0xffffffffu, p, o);
            if ((t & 31) == 0) atomicAdd(&srow[(t >> 7) + 2 * k], p);
        }
        __syncthreads();
        if (t < 8) atomicAdd(&g_acc[2], sqrtf(srow[t]));
    }
}

__device__ __forceinline__ float d2_bf8(uint4 x, uint4 y) {
    float s = 0.f;
    const uint32_t* xp = (const uint32_t*)&x;
    const uint32_t* yp = (const uint32_t*)&y;
#pragma unroll
    for (int qq = 0; qq < 4; qq++) {
        float2 a = __bfloat1622float2(*(const __nv_bfloat162*)&xp[qq]);
        float2 b = __bfloat1622float2(*(const __nv_bfloat162*)&yp[qq]);
        float d0 = a.x - b.x, d1 = a.y - b.y;
        s += d0 * d0 + d1 * d1;
    }
    return s;
}

__global__ void zero_kernel() {
    int i = blockIdx.x * blockDim.x + threadIdx.x;
    if (i < NN) { g_d2sq[i] = 0.f; g_mask[i] = 0; }
    if (i == 0) { g_acc[0] = 0.f; g_acc[1] = 0.f; g_acc[2] = 0.f; }
}

// mask build + bias norms (b1: block 32, b2: block 33)
__global__ void mask_bias_kernel(const int* __restrict__ edges,
                                 const int* __restrict__ labels,
                                 const float* __restrict__ b1,
                                 const float* __restrict__ b2) {
    int b = blockIdx.x;
    if (b < 32) {
        int e = b * 256 + threadIdx.x;
        if (labels[e] != 0) {
            g_mask[edges[2 * e + 0]] = 1;
            g_mask[edges[2 * e + 1]] = 1;
        }
    } else {
        const float* p = (b == 32) ? b1 : b2;
        int len = (b == 32) ? HD : NN;
        float s = 0.f;
        for (int c = threadIdx.x; c < len; c += 256) { float x = p[c]; s += x * x; }
        s = block_reduce(s);
        if (threadIdx.x == 0) atomicAdd(&g_acc[2], sqrtf(s));
    }
}

__global__ void edge_loss_kernel(const int* __restrict__ edges,
                                 const int* __restrict__ labels) {
    int e  = blockIdx.x;
    int ni = edges[2 * e + 0];
    int nj = edges[2 * e + 1];
    int lab = labels[e];

    if (lab != 0) {
        const uint4* hi1 = (const uint4*)(g_H1bf + (size_t)ni * HD);
        const uint4* hj1 = (const uint4*)(g_H1bf + (size_t)nj * HD);
        float s1 = 0.f;
        for (int c = threadIdx.x; c < HD / 8; c += blockDim.x)
            s1 += d2_bf8(hi1[c], hj1[c]);
        const uint4* hi2 = (const uint4*)(g_H2bf + (size_t)ni * NN);
        const uint4* hj2 = (const uint4*)(g_H2bf + (size_t)nj * NN);
        float s2 = 0.f;
        for (int c = threadIdx.x; c < NN / 8; c += blockDim.x)
            s2 += d2_bf8(hi2[c], hj2[c]);
        s1 = block_reduce(s1);
        s2 = block_reduce(s2);
        if (threadIdx.x == 0) atomicAdd(&g_acc[0], sqrtf(s1) + sqrtf(s2));
    }
    if (threadIdx.x == 0) {
        float factor = (lab != 0) ? 10.f : 1.f;
        atomicAdd(&g_acc[1], factor * (sqrtf(g_d2sq[ni]) + sqrtf(g_d2sq[nj])));
    }
}

__global__ void finalize_kernel(float* out) {
    out[0] = g_acc[0] + g_acc[1] + g_acc[2] * (float)EE;
}

// ---------------- launch ----------------
extern "C" void kernel_launch(void* const* d_in, const int* in_sizes, int n_in,
                              void* d_out, int out_size) {
    const float* A      = (const float*)d_in[0];
    const float* W1     = (const float*)d_in[1];
    const float* b1     = (const float*)d_in[2];
    const float* W2     = (const float*)d_in[3];
    const float* b2     = (const float*)d_in[4];
    const int*   edges  = (const int*)d_in[5];
    const int*   labels = (const int*)d_in[6];
    float* out = (float*)d_out;

    __nv_bfloat16 *Abf, *W1bf, *W2bf, *H1bf, *H2bf;
    float* d2sq;
    unsigned char* mask;
    cudaGetSymbolAddress((void**)&Abf,  g_Abf);
    cudaGetSymbolAddress((void**)&W1bf, g_W1bf);
    cudaGetSymbolAddress((void**)&W2bf, g_W2bf);
    cudaGetSymbolAddress((void**)&H1bf, g_H1bf);
    cudaGetSymbolAddress((void**)&H2bf, g_H2bf);
    cudaGetSymbolAddress((void**)&d2sq, g_d2sq);
    cudaGetSymbolAddress((void**)&mask, g_mask);

    cudaFuncSetAttribute(gemm1_hmma,
                         cudaFuncAttributeMaxDynamicSharedMemorySize, G_SMEM);
    cudaFuncSetAttribute(gemm2_fused,
                         cudaFuncAttributeMaxDynamicSharedMemorySize, G_SMEM);

    zero_kernel<<<NN / 256, 256>>>();
    mask_bias_kernel<<<34, 256>>>(edges, labels, b1, b2);

    // merged fp32 -> bf16 conversions (+ W row-norm fold)
    convert_all<<<10240, 256>>>((const float4*)A,  (uint4*)Abf,
                                (const float4*)W1, (uint4*)W1bf,
                                (const float4*)W2, (uint4*)W2bf);

    // H1 = sigmoid(A @ W1^T + b1): M=8192, Nc=1024, K=8192
    gemm1_hmma<<<dim3(HD / 128, NN / 128), 256, G_SMEM>>>(Abf, W1bf, b1, H1bf, NN, HD);
    // H2 = sigmoid(H1 @ W2^T + b2) + fused residual (vs bf16 A), mask-gated stores
    gemm2_fused<<<dim3(NN / 128, NN / 128), 256, G_SMEM>>>(
        H1bf, W2bf, b2, H2bf, Abf, d2sq, mask, HD, NN);

    edge_loss_kernel<<<EE, 256>>>(edges, labels);
    finalize_kernel<<<1, 1>>>(out);
}

// round 14
// speedup vs baseline: 1.0520x; 1.0520x over previous
#include <cuda_runtime.h>
#include <cuda_bf16.h>
#include <cstdint>
#include <math.h>

#define NN 8192
#define HD 1024
#define EE 8192

// ---------------- scratch (device globals; allocation-free) ----------------
__device__ __nv_bfloat16 g_Abf[(size_t)NN * NN];   // 128 MB
__device__ __nv_bfloat16 g_W1bf[(size_t)HD * NN];  // 16 MB
__device__ __nv_bfloat16 g_W2bf[(size_t)NN * HD];  // 16 MB
__device__ __nv_bfloat16 g_H1bf[(size_t)NN * HD];  // 16 MB
__device__ __nv_bfloat16 g_H2bf[(size_t)NN * NN];  // 128 MB
__device__ float g_d2sq[NN];
__device__ float g_acc[3];
__device__ unsigned char g_mask[NN];

// ---------------- PTX helpers ----------------
__device__ __forceinline__ uint32_t smem_u32(const void* p) {
    uint32_t a;
    asm("{ .reg .u64 t; cvta.to.shared.u64 t, %1; cvt.u32.u64 %0, t; }" : "=r"(a) : "l"(p));
    return a;
}

#define CP_ASYNC16(dst, src) \
    asm volatile("cp.async.cg.shared.global [%0], [%1], 16;" :: "r"(dst), "l"(src) : "memory")
#define CP_COMMIT() asm volatile("cp.async.commit_group;" ::: "memory")
template <int N>
__device__ __forceinline__ void cp_wait() {
    asm volatile("cp.async.wait_group %0;" :: "n"(N) : "memory");
}

__device__ __forceinline__ void ldsm4(uint32_t* r, uint32_t addr) {
    asm volatile("ldmatrix.sync.aligned.m8n8.x4.shared.b16 {%0,%1,%2,%3}, [%4];"
                 : "=r"(r[0]), "=r"(r[1]), "=r"(r[2]), "=r"(r[3]) : "r"(addr));
}

__device__ __forceinline__ void mma_bf16(float* c, const uint32_t* a,
                                         uint32_t b0, uint32_t b1) {
    asm volatile(
        "mma.sync.aligned.m16n8k16.row.col.f32.bf16.bf16.f32 "
        "{%0,%1,%2,%3}, {%4,%5,%6,%7}, {%8,%9}, {%0,%1,%2,%3};"
        : "+f"(c[0]), "+f"(c[1]), "+f"(c[2]), "+f"(c[3])
        : "r"(a[0]), "r"(a[1]), "r"(a[2]), "r"(a[3]), "r"(b0), "r"(b1));
}

__device__ __forceinline__ uint32_t sw128(uint32_t off) {
    return off ^ ((off >> 3) & 0x70);
}

// shared stage loader: A tile 128x64 bf16 + B tile 128x64 bf16, SW128 swizzled
__device__ __forceinline__ void load_stage(
    const __nv_bfloat16* __restrict__ Abf, const __nv_bfloat16* __restrict__ Bbf,
    int K, int bm0, int bn0, int kt, uint32_t stageBase, int tid)
{
#pragma unroll
    for (int r = 0; r < 4; r++) {
        int idx = tid + r * 256;
        int row = idx >> 3, ck = idx & 7;
        uint32_t sw = sw128((uint32_t)(row * 128 + ck * 16));
        const void* srcA = (const char*)(Abf + (size_t)(bm0 + row) * K + kt) + ck * 16;
        CP_ASYNC16(stageBase + sw, srcA);
        const void* srcB = (const char*)(Bbf + (size_t)(bn0 + row) * K + kt) + ck * 16;
        CP_ASYNC16(stageBase + 16384 + sw, srcB);
    }
    CP_COMMIT();
}

#define STAGE_BYTES 32768
#define G_SMEM (2 * STAGE_BYTES)

// =======================================================================
// GEMM1: 2-stage pipeline, 64KB smem, 2 CTAs/SM (R12 champion config)
// =======================================================================
__global__ void __launch_bounds__(256, 2)
gemm1_hmma(const __nv_bfloat16* __restrict__ Abf,
           const __nv_bfloat16* __restrict__ Bbf,
           const float* __restrict__ bias,
           __nv_bfloat16* __restrict__ Hout,
           int K, int Nc)
{
    extern __shared__ __align__(1024) char smem[];
    const uint32_t sb0 = smem_u32(smem);
    const int tid = threadIdx.x;
    const int wid = tid >> 5, lid = tid & 31;
    const int warp_m = wid >> 2;
    const int warp_n = wid & 3;
    const int bm0 = blockIdx.y * 128;
    const int bn0 = blockIdx.x * 128;

    const int q  = lid >> 3;
    const int r8 = lid & 7;
    const int arowb = warp_m * 64 + (q & 1) * 8 + r8;
    const int browb = warp_n * 32 + (q & 1) * 8 + r8;
    const uint32_t kq   = (uint32_t)((q >> 1) * 16);
    const uint32_t axor = (uint32_t)((arowb & 7) << 4);
    const uint32_t bxor = (uint32_t)((browb & 7) << 4);

    float acc[4][4][4];
#pragma unroll
    for (int i = 0; i < 4; i++)
#pragma unroll
        for (int j = 0; j < 4; j++)
#pragma unroll
            for (int k = 0; k < 4; k++) acc[i][j][k] = 0.f;

    const int T = K >> 6;

    load_stage(Abf, Bbf, K, bm0, bn0, 0, sb0, tid);

    for (int i = 0; i < T; i++) {
        if (i + 1 < T)
            load_stage(Abf, Bbf, K, bm0, bn0, (i + 1) * 64,
                       sb0 + (uint32_t)((i + 1) & 1) * STAGE_BYTES, tid);
        if (i + 1 < T) cp_wait<1>(); else cp_wait<0>();
        __syncthreads();

        const uint32_t Ab = sb0 + (uint32_t)(i & 1) * STAGE_BYTES;
        const uint32_t Bb = Ab + 16384;

#pragma unroll
        for (int s = 0; s < 4; s++) {
            const uint32_t koff = (uint32_t)(s * 32) | kq;
            uint32_t a[4][4], bfr[2][4];
#pragma unroll
            for (int mt = 0; mt < 4; mt++)
                ldsm4(a[mt], Ab + (uint32_t)(arowb + mt * 16) * 128 + (koff ^ axor));
#pragma unroll
            for (int bt = 0; bt < 2; bt++)
                ldsm4(bfr[bt], Bb + (uint32_t)(browb + bt * 16) * 128 + (koff ^ bxor));
#pragma unroll
            for (int mt = 0; mt < 4; mt++)
#pragma unroll
                for (int nt = 0; nt < 4; nt++)
                    mma_bf16(acc[mt][nt], a[mt], bfr[nt >> 1][nt & 1], bfr[nt >> 1][(nt & 1) + 2]);
        }
        __syncthreads();
    }

    const int rr = lid >> 2;
    const int cc = (lid & 3) * 2;
#pragma unroll
    for (int nt = 0; nt < 4; nt++) {
        const int col = bn0 + warp_n * 32 + nt * 8 + cc;
        const float bb0 = bias[col], bb1 = bias[col + 1];
#pragma unroll
        for (int mt = 0; mt < 4; mt++) {
            const int row0 = bm0 + warp_m * 64 + mt * 16 + rr;
            float v0 = acc[mt][nt][0] + bb0, v1 = acc[mt][nt][1] + bb1;
            float v2 = acc[mt][nt][2] + bb0, v3 = acc[mt][nt][3] + bb1;
            float s0 = 1.f / (1.f + __expf(-v0));
            float s1 = 1.f / (1.f + __expf(-v1));
            float s2 = 1.f / (1.f + __expf(-v2));
            float s3 = 1.f / (1.f + __expf(-v3));
            __nv_bfloat162 h01 = __floats2bfloat162_rn(s0, s1);
            __nv_bfloat162 h23 = __floats2bfloat162_rn(s2, s3);
            *(uint32_t*)(Hout + (size_t)row0 * Nc + col)       = *(uint32_t*)&h01;
            *(uint32_t*)(Hout + (size_t)(row0 + 8) * Nc + col) = *(uint32_t*)&h23;
        }
    }
}

// =======================================================================
// GEMM2: 2-stage, 2 CTAs/SM, fused residual (vs bf16 A) + mask-gated stores
// =======================================================================
__global__ void __launch_bounds__(256, 2)
gemm2_fused(const __nv_bfloat16* __restrict__ Abf,
            const __nv_bfloat16* __restrict__ Bbf,
            const float* __restrict__ bias,
            __nv_bfloat16* __restrict__ Hout,
            const __nv_bfloat16* __restrict__ Aref,
            float* __restrict__ d2sq,
            const unsigned char* __restrict__ mask,
            int K, int Nc)
{
    extern __shared__ __align__(1024) char smem[];
    const uint32_t sb0 = smem_u32(smem);
    const int tid = threadIdx.x;
    const int wid = tid >> 5, lid = tid & 31;
    const int warp_m = wid >> 2;
    const int warp_n = wid & 3;
    const int bm0 = blockIdx.y * 128;
    const int bn0 = blockIdx.x * 128;

    const int q  = lid >> 3;
    const int r8 = lid & 7;
    const int arowb = warp_m * 64 + (q & 1) * 8 + r8;
    const int browb = warp_n * 32 + (q & 1) * 8 + r8;
    const uint32_t kq   = (uint32_t)((q >> 1) * 16);
    const uint32_t axor = (uint32_t)((arowb & 7) << 4);
    const uint32_t bxor = (uint32_t)((browb & 7) << 4);

    float acc[4][4][4];
#pragma unroll
    for (int i = 0; i < 4; i++)
#pragma unroll
        for (int j = 0; j < 4; j++)
#pragma unroll
            for (int k = 0; k < 4; k++) acc[i][j][k] = 0.f;

    const int T = K >> 6;   // 16

    load_stage(Abf, Bbf, K, bm0, bn0, 0, sb0, tid);

    for (int i = 0; i < T; i++) {
        if (i + 1 < T)
            load_stage(Abf, Bbf, K, bm0, bn0, (i + 1) * 64,
                       sb0 + (uint32_t)((i + 1) & 1) * STAGE_BYTES, tid);
        if (i + 1 < T) cp_wait<1>(); else cp_wait<0>();
        __syncthreads();

        const uint32_t Ab = sb0 + (uint32_t)(i & 1) * STAGE_BYTES;
        const uint32_t Bb = Ab + 16384;

#pragma unroll
        for (int s = 0; s < 4; s++) {
            const uint32_t koff = (uint32_t)(s * 32) | kq;
            uint32_t a[4][4], bfr[2][4];
#pragma unroll
            for (int mt = 0; mt < 4; mt++)
                ldsm4(a[mt], Ab + (uint32_t)(arowb + mt * 16) * 128 + (koff ^ axor));
#pragma unroll
            for (int bt = 0; bt < 2; bt++)
                ldsm4(bfr[bt], Bb + (uint32_t)(browb + bt * 16) * 128 + (koff ^ bxor));
#pragma unroll
            for (int mt = 0; mt < 4; mt++)
#pragma unroll
                for (int nt = 0; nt < 4; nt++)
                    mma_bf16(acc[mt][nt], a[mt], bfr[nt >> 1][nt & 1], bfr[nt >> 1][(nt & 1) + 2]);
        }
        __syncthreads();
    }

    const int rr = lid >> 2;
    const int cc = (lid & 3) * 2;
    float sum0[4] = {0.f, 0.f, 0.f, 0.f};
    float sum8[4] = {0.f, 0.f, 0.f, 0.f};
    bool m0[4], m8[4];
#pragma unroll
    for (int mt = 0; mt < 4; mt++) {
        const int row0 = bm0 + warp_m * 64 + mt * 16 + rr;
        m0[mt] = mask[row0] != 0;
        m8[mt] = mask[row0 + 8] != 0;
    }

#pragma unroll
    for (int nt = 0; nt < 4; nt++) {
        const int col = bn0 + warp_n * 32 + nt * 8 + cc;
        const float bb0 = bias[col], bb1 = bias[col + 1];
#pragma unroll
        for (int mt = 0; mt < 4; mt++) {
            const int row0 = bm0 + warp_m * 64 + mt * 16 + rr;
            float v0 = acc[mt][nt][0] + bb0, v1 = acc[mt][nt][1] + bb1;
            float v2 = acc[mt][nt][2] + bb0, v3 = acc[mt][nt][3] + bb1;
            float s0 = 1.f / (1.f + __expf(-v0));
            float s1 = 1.f / (1.f + __expf(-v1));
            float s2 = 1.f / (1.f + __expf(-v2));
            float s3 = 1.f / (1.f + __expf(-v3));
            uint32_t a01u = __ldcs((const uint32_t*)(Aref + (size_t)row0 * Nc + col));
            uint32_t a23u = __ldcs((const uint32_t*)(Aref + (size_t)(row0 + 8) * Nc + col));
            float2 a01 = __bfloat1622float2(*(const __nv_bfloat162*)&a01u);
            float2 a23 = __bfloat1622float2(*(const __nv_bfloat162*)&a23u);
            float d0 = a01.x - s0, d1 = a01.y - s1;
            float d2v = a23.x - s2, d3 = a23.y - s3;
            sum0[mt] += d0 * d0 + d1 * d1;
            sum8[mt] += d2v * d2v + d3 * d3;
            if (m0[mt]) {
                __nv_bfloat162 h01 = __floats2bfloat162_rn(s0, s1);
                __stcs((unsigned int*)(Hout + (size_t)row0 * Nc + col), *(unsigned int*)&h01);
            }
            if (m8[mt]) {
                __nv_bfloat162 h23 = __floats2bfloat162_rn(s2, s3);
                __stcs((unsigned int*)(Hout + (size_t)(row0 + 8) * Nc + col), *(unsigned int*)&h23);
            }
        }
    }

#pragma unroll
    for (int mt = 0; mt < 4; mt++) {
        float s0v = sum0[mt], s8v = sum8[mt];
        s0v += __shfl_xor_sync(0xffffffffu, s0v, 1);
        s0v += __shfl_xor_sync(0xffffffffu, s0v, 2);
        s8v += __shfl_xor_sync(0xffffffffu, s8v, 1);
        s8v += __shfl_xor_sync(0xffffffffu, s8v, 2);
        if ((lid & 3) == 0) {
            const int row0 = bm0 + warp_m * 64 + mt * 16 + rr;
            atomicAdd(&d2sq[row0], s0v);
            atomicAdd(&d2sq[row0 + 8], s8v);
        }
    }
}

// ---------------- block reduction (256 threads) ----------------
__device__ __forceinline__ float block_reduce(float v) {
    __shared__ float sh[8];
    __syncthreads();
    int lane = threadIdx.x & 31;
    int w    = threadIdx.x >> 5;
#pragma unroll
    for (int o = 16; o > 0; o >>= 1) v += __shfl_down_sync(0xffffffffu, v, o);
    if (lane == 0) sh[w] = v;
    __syncthreads();
    if (w == 0) {
        v = (lane < 8) ? sh[lane] : 0.f;
#pragma unroll
        for (int o = 4; o > 0; o >>= 1) v += __shfl_down_sync(0xffffffffu, v, o);
    }
    return v;
}

// ---------------- merged fp32 -> bf16 conversion + W row-norm fold ----------
__global__ void convert_all(const float4* __restrict__ A, uint4* __restrict__ Abf,
                            const float4* __restrict__ W1, uint4* __restrict__ W1bf,
                            const float4* __restrict__ W2, uint4* __restrict__ W2bf)
{
    const float4* in;
    uint4* out;
    int b = blockIdx.x;
    int which;
    if (b < 8192)      { in = A;  out = Abf;  which = 0; }
    else if (b < 9216) { in = W1; out = W1bf; which = 1; b -= 8192; }
    else               { in = W2; out = W2bf; which = 2; b -= 9216; }
    const int t = threadIdx.x;
    float4 v[8];
#pragma unroll
    for (int k = 0; k < 4; k++) {
        int i = b * 2048 + t * 2 + k * 512;
        v[2 * k]     = __ldcs(in + i);
        v[2 * k + 1] = __ldcs(in + i + 1);
    }
#pragma unroll
    for (int k = 0; k < 4; k++) {
        __nv_bfloat162 a0 = __floats2bfloat162_rn(v[2 * k].x,     v[2 * k].y);
        __nv_bfloat162 a1 = __floats2bfloat162_rn(v[2 * k].z,     v[2 * k].w);
        __nv_bfloat162 a2 = __floats2bfloat162_rn(v[2 * k + 1].x, v[2 * k + 1].y);
        __nv_bfloat162 a3 = __floats2bfloat162_rn(v[2 * k + 1].z, v[2 * k + 1].w);
        __stcs(out + b * 1024 + t + k * 256,
               make_uint4(*(uint32_t*)&a0, *(uint32_t*)&a1,
                          *(uint32_t*)&a2, *(uint32_t*)&a3));
    }

    if (which == 1) {
        float s = 0.f;
#pragma unroll
        for (int k = 0; k < 8; k++)
            s += v[k].x * v[k].x + v[k].y * v[k].y + v[k].z * v[k].z + v[k].w * v[k].w;
        s = block_reduce(s);
        if (t == 0) atomicAdd(&g_acc[2], sqrtf(s));
    } else if (which == 2) {
        __shared__ float srow[8];
        if (t < 8) srow[t] = 0.f;
        __syncthreads();
#pragma unroll
        for (int k = 0; k < 4; k++) {
            float p = v[2 * k].x * v[2 * k].x + v[2 * k].y * v[2 * k].y
                    + v[2 * k].z * v[2 * k].z + v[2 * k].w * v[2 * k].w
                    + v[2 * k + 1].x * v[2 * k + 1].x + v[2 * k + 1].y * v[2 * k + 1].y
                    + v[2 * k + 1].z * v[2 * k + 1].z + v[2 * k + 1].w * v[2 * k + 1].w;
#pragma unroll
            for (int o = 16; o > 0; o >>= 1) p += __shfl_xor_sync(0xffffffffu, p, o);
            if ((t & 31) == 0) atomicAdd(&srow[(t >> 7) + 2 * k], p);
        }
        __syncthreads();
        if (t < 8) atomicAdd(&g_acc[2], sqrtf(srow[t]));
    }
}

__device__ __forceinline__ float d2_bf8(uint4 x, uint4 y) {
    float s = 0.f;
    const uint32_t* xp = (const uint32_t*)&x;
    const uint32_t* yp = (const uint32_t*)&y;
#pragma unroll
    for (int qq = 0; qq < 4; qq++) {
        float2 a = __bfloat1622float2(*(const __nv_bfloat162*)&xp[qq]);
        float2 b = __bfloat1622float2(*(const __nv_bfloat162*)&yp[qq]);
        float d0 = a.x - b.x, d1 = a.y - b.y;
        s += d0 * d0 + d1 * d1;
    }
    return s;
}

__global__ void zero_kernel() {
    int i = blockIdx.x * blockDim.x + threadIdx.x;
    if (i < NN) { g_d2sq[i] = 0.f; g_mask[i] = 0; }
    if (i == 0) { g_acc[0] = 0.f; g_acc[1] = 0.f; g_acc[2] = 0.f; }
}

// mask build + bias norms (b1: block 32, b2: block 33)
__global__ void mask_bias_kernel(const int* __restrict__ edges,
                                 const int* __restrict__ labels,
                                 const float* __restrict__ b1,
                                 const float* __restrict__ b2) {
    int b = blockIdx.x;
    if (b < 32) {
        int e = b * 256 + threadIdx.x;
        if (labels[e] != 0) {
            g_mask[edges[2 * e + 0]] = 1;
            g_mask[edges[2 * e + 1]] = 1;
        }
    } else {
        const float* p = (b == 32) ? b1 : b2;
        int len = (b == 32) ? HD : NN;
        float s = 0.f;
        for (int c = threadIdx.x; c < len; c += 256) { float x = p[c]; s += x * x; }
        s = block_reduce(s);
        if (threadIdx.x == 0) atomicAdd(&g_acc[2], sqrtf(s));
    }
}

// edge losses; H2 reads batched (MLP=8) with streaming hint
__global__ void edge_loss_kernel(const int* __restrict__ edges,
                                 const int* __restrict__ labels) {
    int e  = blockIdx.x;
    int ni = edges[2 * e + 0];
    int nj = edges[2 * e + 1];
    int lab = labels[e];

    if (lab != 0) {
        const int t = threadIdx.x;
        // H1 distances (L2-resident, 16 MB)
        const uint4* hi1 = (const uint4*)(g_H1bf + (size_t)ni * HD);
        const uint4* hj1 = (const uint4*)(g_H1bf + (size_t)nj * HD);
        float s1 = 0.f;
        {
            // HD/8 = 128 chunks; 256 threads -> threads t<128 take one chunk
            if (t < 128) s1 = d2_bf8(__ldca(hi1 + t), __ldca(hj1 + t));
        }
        // H2 distances (DRAM): batch all 8 independent loads up front
        const uint4* hi2 = (const uint4*)(g_H2bf + (size_t)ni * NN);
        const uint4* hj2 = (const uint4*)(g_H2bf + (size_t)nj * NN);
        uint4 xi[4], xj[4];
#pragma unroll
        for (int k = 0; k < 4; k++) {
            int c = t + k * 256;          // NN/8 = 1024 chunks
            xi[k] = __ldcs(hi2 + c);
            xj[k] = __ldcs(hj2 + c);
        }
        float s2 = 0.f;
#pragma unroll
        for (int k = 0; k < 4; k++) s2 += d2_bf8(xi[k], xj[k]);

        s1 = block_reduce(s1);
        s2 = block_reduce(s2);
        if (t == 0) atomicAdd(&g_acc[0], sqrtf(s1) + sqrtf(s2));
    }
    if (threadIdx.x == 0) {
        float factor = (lab != 0) ? 10.f : 1.f;
        atomicAdd(&g_acc[1], factor * (sqrtf(g_d2sq[ni]) + sqrtf(g_d2sq[nj])));
    }
}

__global__ void finalize_kernel(float* out) {
    out[0] = g_acc[0] + g_acc[1] + g_acc[2] * (float)EE;
}

// ---------------- launch ----------------
extern "C" void kernel_launch(void* const* d_in, const int* in_sizes, int n_in,
                              void* d_out, int out_size) {
    const float* A      = (const float*)d_in[0];
    const float* W1     = (const float*)d_in[1];
    const float* b1     = (const float*)d_in[2];
    const float* W2     = (const float*)d_in[3];
    const float* b2     = (const float*)d_in[4];
    const int*   edges  = (const int*)d_in[5];
    const int*   labels = (const int*)d_in[6];
    float* out = (float*)d_out;

    __nv_bfloat16 *Abf, *W1bf, *W2bf, *H1bf, *H2bf;
    float* d2sq;
    unsigned char* mask;
    cudaGetSymbolAddress((void**)&Abf,  g_Abf);
    cudaGetSymbolAddress((void**)&W1bf, g_W1bf);
    cudaGetSymbolAddress((void**)&W2bf, g_W2bf);
    cudaGetSymbolAddress((void**)&H1bf, g_H1bf);
    cudaGetSymbolAddress((void**)&H2bf, g_H2bf);
    cudaGetSymbolAddress((void**)&d2sq, g_d2sq);
    cudaGetSymbolAddress((void**)&mask, g_mask);

    cudaFuncSetAttribute(gemm1_hmma,
                         cudaFuncAttributeMaxDynamicSharedMemorySize, G_SMEM);
    cudaFuncSetAttribute(gemm2_fused,
                         cudaFuncAttributeMaxDynamicSharedMemorySize, G_SMEM);

    zero_kernel<<<NN / 256, 256>>>();
    mask_bias_kernel<<<34, 256>>>(edges, labels, b1, b2);

    // merged fp32 -> bf16 conversions (+ W row-norm fold)
    convert_all<<<10240, 256>>>((const float4*)A,  (uint4*)Abf,
                                (const float4*)W1, (uint4*)W1bf,
                                (const float4*)W2, (uint4*)W2bf);

    // H1 = sigmoid(A @ W1^T + b1): M=8192, Nc=1024, K=8192
    gemm1_hmma<<<dim3(HD / 128, NN / 128), 256, G_SMEM>>>(Abf, W1bf, b1, H1bf, NN, HD);
    // H2 = sigmoid(H1 @ W2^T + b2) + fused residual (vs bf16 A), mask-gated stores
    gemm2_fused<<<dim3(NN / 128, NN / 128), 256, G_SMEM>>>(
        H1bf, W2bf, b2, H2bf, Abf, d2sq, mask, HD, NN);

    edge_loss_kernel<<<EE, 256>>>(edges, labels);
    finalize_kernel<<<1, 1>>>(out);
}

// round 15
// speedup vs baseline: 1.0540x; 1.0019x over previous
#include <cuda_runtime.h>
#include <cuda_bf16.h>
#include <cuda_fp16.h>
#include <cuda_fp8.h>
#include <cstdint>
#include <math.h>

#define NN 8192
#define HD 1024
#define EE 8192

// ---------------- scratch (device globals; allocation-free) ----------------
__device__ __nv_bfloat16 g_Abf[(size_t)NN * NN];   // 128 MB
__device__ __nv_bfloat16 g_W1bf[(size_t)HD * NN];  // 16 MB
__device__ __nv_bfloat16 g_W2bf[(size_t)NN * HD];  // 16 MB
__device__ __nv_bfloat16 g_H1bf[(size_t)NN * HD];  // 16 MB
__device__ unsigned char g_H28[(size_t)NN * NN];   // 64 MB (fp8 e4m3 H2)
__device__ float g_d2sq[NN];
__device__ float g_acc[3];
__device__ unsigned char g_mask[NN];

// ---------------- PTX helpers ----------------
__device__ __forceinline__ uint32_t smem_u32(const void* p) {
    uint32_t a;
    asm("{ .reg .u64 t; cvta.to.shared.u64 t, %1; cvt.u32.u64 %0, t; }" : "=r"(a) : "l"(p));
    return a;
}

#define CP_ASYNC16(dst, src) \
    asm volatile("cp.async.cg.shared.global [%0], [%1], 16;" :: "r"(dst), "l"(src) : "memory")
#define CP_COMMIT() asm volatile("cp.async.commit_group;" ::: "memory")
template <int N>
__device__ __forceinline__ void cp_wait() {
    asm volatile("cp.async.wait_group %0;" :: "n"(N) : "memory");
}

__device__ __forceinline__ void ldsm4(uint32_t* r, uint32_t addr) {
    asm volatile("ldmatrix.sync.aligned.m8n8.x4.shared.b16 {%0,%1,%2,%3}, [%4];"
                 : "=r"(r[0]), "=r"(r[1]), "=r"(r[2]), "=r"(r[3]) : "r"(addr));
}

__device__ __forceinline__ void mma_bf16(float* c, const uint32_t* a,
                                         uint32_t b0, uint32_t b1) {
    asm volatile(
        "mma.sync.aligned.m16n8k16.row.col.f32.bf16.bf16.f32 "
        "{%0,%1,%2,%3}, {%4,%5,%6,%7}, {%8,%9}, {%0,%1,%2,%3};"
        : "+f"(c[0]), "+f"(c[1]), "+f"(c[2]), "+f"(c[3])
        : "r"(a[0]), "r"(a[1]), "r"(a[2]), "r"(a[3]), "r"(b0), "r"(b1));
}

__device__ __forceinline__ uint32_t sw128(uint32_t off) {
    return off ^ ((off >> 3) & 0x70);
}

// shared stage loader: A tile 128x64 bf16 + B tile 128x64 bf16, SW128 swizzled
__device__ __forceinline__ void load_stage(
    const __nv_bfloat16* __restrict__ Abf, const __nv_bfloat16* __restrict__ Bbf,
    int K, int bm0, int bn0, int kt, uint32_t stageBase, int tid)
{
#pragma unroll
    for (int r = 0; r < 4; r++) {
        int idx = tid + r * 256;
        int row = idx >> 3, ck = idx & 7;
        uint32_t sw = sw128((uint32_t)(row * 128 + ck * 16));
        const void* srcA = (const char*)(Abf + (size_t)(bm0 + row) * K + kt) + ck * 16;
        CP_ASYNC16(stageBase + sw, srcA);
        const void* srcB = (const char*)(Bbf + (size_t)(bn0 + row) * K + kt) + ck * 16;
        CP_ASYNC16(stageBase + 16384 + sw, srcB);
    }
    CP_COMMIT();
}

#define STAGE_BYTES 32768
#define G_SMEM (2 * STAGE_BYTES)

// =======================================================================
// GEMM1: 2-stage pipeline, 64KB smem, 2 CTAs/SM (champion config)
// =======================================================================
__global__ void __launch_bounds__(256, 2)
gemm1_hmma(const __nv_bfloat16* __restrict__ Abf,
           const __nv_bfloat16* __restrict__ Bbf,
           const float* __restrict__ bias,
           __nv_bfloat16* __restrict__ Hout,
           int K, int Nc)
{
    extern __shared__ __align__(1024) char smem[];
    const uint32_t sb0 = smem_u32(smem);
    const int tid = threadIdx.x;
    const int wid = tid >> 5, lid = tid & 31;
    const int warp_m = wid >> 2;
    const int warp_n = wid & 3;
    const int bm0 = blockIdx.y * 128;
    const int bn0 = blockIdx.x * 128;

    const int q  = lid >> 3;
    const int r8 = lid & 7;
    const int arowb = warp_m * 64 + (q & 1) * 8 + r8;
    const int browb = warp_n * 32 + (q & 1) * 8 + r8;
    const uint32_t kq   = (uint32_t)((q >> 1) * 16);
    const uint32_t axor = (uint32_t)((arowb & 7) << 4);
    const uint32_t bxor = (uint32_t)((browb & 7) << 4);

    float acc[4][4][4];
#pragma unroll
    for (int i = 0; i < 4; i++)
#pragma unroll
        for (int j = 0; j < 4; j++)
#pragma unroll
            for (int k = 0; k < 4; k++) acc[i][j][k] = 0.f;

    const int T = K >> 6;

    load_stage(Abf, Bbf, K, bm0, bn0, 0, sb0, tid);

    for (int i = 0; i < T; i++) {
        if (i + 1 < T)
            load_stage(Abf, Bbf, K, bm0, bn0, (i + 1) * 64,
                       sb0 + (uint32_t)((i + 1) & 1) * STAGE_BYTES, tid);
        if (i + 1 < T) cp_wait<1>(); else cp_wait<0>();
        __syncthreads();

        const uint32_t Ab = sb0 + (uint32_t)(i & 1) * STAGE_BYTES;
        const uint32_t Bb = Ab + 16384;

#pragma unroll
        for (int s = 0; s < 4; s++) {
            const uint32_t koff = (uint32_t)(s * 32) | kq;
            uint32_t a[4][4], bfr[2][4];
#pragma unroll
            for (int mt = 0; mt < 4; mt++)
                ldsm4(a[mt], Ab + (uint32_t)(arowb + mt * 16) * 128 + (koff ^ axor));
#pragma unroll
            for (int bt = 0; bt < 2; bt++)
                ldsm4(bfr[bt], Bb + (uint32_t)(browb + bt * 16) * 128 + (koff ^ bxor));
#pragma unroll
            for (int mt = 0; mt < 4; mt++)
#pragma unroll
                for (int nt = 0; nt < 4; nt++)
                    mma_bf16(acc[mt][nt], a[mt], bfr[nt >> 1][nt & 1], bfr[nt >> 1][(nt & 1) + 2]);
        }
        __syncthreads();
    }

    const int rr = lid >> 2;
    const int cc = (lid & 3) * 2;
#pragma unroll
    for (int nt = 0; nt < 4; nt++) {
        const int col = bn0 + warp_n * 32 + nt * 8 + cc;
        const float bb0 = bias[col], bb1 = bias[col + 1];
#pragma unroll
        for (int mt = 0; mt < 4; mt++) {
            const int row0 = bm0 + warp_m * 64 + mt * 16 + rr;
            float v0 = acc[mt][nt][0] + bb0, v1 = acc[mt][nt][1] + bb1;
            float v2 = acc[mt][nt][2] + bb0, v3 = acc[mt][nt][3] + bb1;
            float s0 = 1.f / (1.f + __expf(-v0));
            float s1 = 1.f / (1.f + __expf(-v1));
            float s2 = 1.f / (1.f + __expf(-v2));
            float s3 = 1.f / (1.f + __expf(-v3));
            __nv_bfloat162 h01 = __floats2bfloat162_rn(s0, s1);
            __nv_bfloat162 h23 = __floats2bfloat162_rn(s2, s3);
            *(uint32_t*)(Hout + (size_t)row0 * Nc + col)       = *(uint32_t*)&h01;
            *(uint32_t*)(Hout + (size_t)(row0 + 8) * Nc + col) = *(uint32_t*)&h23;
        }
    }
}

// =======================================================================
// GEMM2: 2-stage, 2 CTAs/SM, fused residual (vs bf16 A),
// mask-gated fp8 H2 stores
// =======================================================================
__global__ void __launch_bounds__(256, 2)
gemm2_fused(const __nv_bfloat16* __restrict__ Abf,
            const __nv_bfloat16* __restrict__ Bbf,
            const float* __restrict__ bias,
            unsigned char* __restrict__ Hout8,
            const __nv_bfloat16* __restrict__ Aref,
            float* __restrict__ d2sq,
            const unsigned char* __restrict__ mask,
            int K, int Nc)
{
    extern __shared__ __align__(1024) char smem[];
    const uint32_t sb0 = smem_u32(smem);
    const int tid = threadIdx.x;
    const int wid = tid >> 5, lid = tid & 31;
    const int warp_m = wid >> 2;
    const int warp_n = wid & 3;
    const int bm0 = blockIdx.y * 128;
    const int bn0 = blockIdx.x * 128;

    const int q  = lid >> 3;
    const int r8 = lid & 7;
    const int arowb = warp_m * 64 + (q & 1) * 8 + r8;
    const int browb = warp_n * 32 + (q & 1) * 8 + r8;
    const uint32_t kq   = (uint32_t)((q >> 1) * 16);
    const uint32_t axor = (uint32_t)((arowb & 7) << 4);
    const uint32_t bxor = (uint32_t)((browb & 7) << 4);

    float acc[4][4][4];
#pragma unroll
    for (int i = 0; i < 4; i++)
#pragma unroll
        for (int j = 0; j < 4; j++)
#pragma unroll
            for (int k = 0; k < 4; k++) acc[i][j][k] = 0.f;

    const int T = K >> 6;   // 16

    load_stage(Abf, Bbf, K, bm0, bn0, 0, sb0, tid);

    for (int i = 0; i < T; i++) {
        if (i + 1 < T)
            load_stage(Abf, Bbf, K, bm0, bn0, (i + 1) * 64,
                       sb0 + (uint32_t)((i + 1) & 1) * STAGE_BYTES, tid);
        if (i + 1 < T) cp_wait<1>(); else cp_wait<0>();
        __syncthreads();

        const uint32_t Ab = sb0 + (uint32_t)(i & 1) * STAGE_BYTES;
        const uint32_t Bb = Ab + 16384;

#pragma unroll
        for (int s = 0; s < 4; s++) {
            const uint32_t koff = (uint32_t)(s * 32) | kq;
            uint32_t a[4][4], bfr[2][4];
#pragma unroll
            for (int mt = 0; mt < 4; mt++)
                ldsm4(a[mt], Ab + (uint32_t)(arowb + mt * 16) * 128 + (koff ^ axor));
#pragma unroll
            for (int bt = 0; bt < 2; bt++)
                ldsm4(bfr[bt], Bb + (uint32_t)(browb + bt * 16) * 128 + (koff ^ bxor));
#pragma unroll
            for (int mt = 0; mt < 4; mt++)
#pragma unroll
                for (int nt = 0; nt < 4; nt++)
                    mma_bf16(acc[mt][nt], a[mt], bfr[nt >> 1][nt & 1], bfr[nt >> 1][(nt & 1) + 2]);
        }
        __syncthreads();
    }

    const int rr = lid >> 2;
    const int cc = (lid & 3) * 2;
    float sum0[4] = {0.f, 0.f, 0.f, 0.f};
    float sum8[4] = {0.f, 0.f, 0.f, 0.f};
    bool m0[4], m8[4];
#pragma unroll
    for (int mt = 0; mt < 4; mt++) {
        const int row0 = bm0 + warp_m * 64 + mt * 16 + rr;
        m0[mt] = mask[row0] != 0;
        m8[mt] = mask[row0 + 8] != 0;
    }

#pragma unroll
    for (int nt = 0; nt < 4; nt++) {
        const int col = bn0 + warp_n * 32 + nt * 8 + cc;
        const float bb0 = bias[col], bb1 = bias[col + 1];
#pragma unroll
        for (int mt = 0; mt < 4; mt++) {
            const int row0 = bm0 + warp_m * 64 + mt * 16 + rr;
            float v0 = acc[mt][nt][0] + bb0, v1 = acc[mt][nt][1] + bb1;
            float v2 = acc[mt][nt][2] + bb0, v3 = acc[mt][nt][3] + bb1;
            float s0 = 1.f / (1.f + __expf(-v0));
            float s1 = 1.f / (1.f + __expf(-v1));
            float s2 = 1.f / (1.f + __expf(-v2));
            float s3 = 1.f / (1.f + __expf(-v3));
            uint32_t a01u = __ldcs((const uint32_t*)(Aref + (size_t)row0 * Nc + col));
            uint32_t a23u = __ldcs((const uint32_t*)(Aref + (size_t)(row0 + 8) * Nc + col));
            float2 a01 = __bfloat1622float2(*(const __nv_bfloat162*)&a01u);
            float2 a23 = __bfloat1622float2(*(const __nv_bfloat162*)&a23u);
            float d0 = a01.x - s0, d1 = a01.y - s1;
            float d2v = a23.x - s2, d3 = a23.y - s3;
            sum0[mt] += d0 * d0 + d1 * d1;
            sum8[mt] += d2v * d2v + d3 * d3;
            if (m0[mt]) {
                __nv_fp8x2_storage_t f01 = __nv_cvt_float2_to_fp8x2(
                    make_float2(s0, s1), __NV_SATFINITE, __NV_E4M3);
                *(unsigned short*)(Hout8 + (size_t)row0 * Nc + col) = (unsigned short)f01;
            }
            if (m8[mt]) {
                __nv_fp8x2_storage_t f23 = __nv_cvt_float2_to_fp8x2(
                    make_float2(s2, s3), __NV_SATFINITE, __NV_E4M3);
                *(unsigned short*)(Hout8 + (size_t)(row0 + 8) * Nc + col) = (unsigned short)f23;
            }
        }
    }

#pragma unroll
    for (int mt = 0; mt < 4; mt++) {
        float s0v = sum0[mt], s8v = sum8[mt];
        s0v += __shfl_xor_sync(0xffffffffu, s0v, 1);
        s0v += __shfl_xor_sync(0xffffffffu, s0v, 2);
        s8v += __shfl_xor_sync(0xffffffffu, s8v, 1);
        s8v += __shfl_xor_sync(0xffffffffu, s8v, 2);
        if ((lid & 3) == 0) {
            const int row0 = bm0 + warp_m * 64 + mt * 16 + rr;
            atomicAdd(&d2sq[row0], s0v);
            atomicAdd(&d2sq[row0 + 8], s8v);
        }
    }
}

// ---------------- block reduction (256 threads) ----------------
__device__ __forceinline__ float block_reduce(float v) {
    __shared__ float sh[8];
    __syncthreads();
    int lane = threadIdx.x & 31;
    int w    = threadIdx.x >> 5;
#pragma unroll
    for (int o = 16; o > 0; o >>= 1) v += __shfl_down_sync(0xffffffffu, v, o);
    if (lane == 0) sh[w] = v;
    __syncthreads();
    if (w == 0) {
        v = (lane < 8) ? sh[lane] : 0.f;
#pragma unroll
        for (int o = 4; o > 0; o >>= 1) v += __shfl_down_sync(0xffffffffu, v, o);
    }
    return v;
}

// ---------------- merged fp32 -> bf16 conversion + W row-norm fold ----------
__global__ void convert_all(const float4* __restrict__ A, uint4* __restrict__ Abf,
                            const float4* __restrict__ W1, uint4* __restrict__ W1bf,
                            const float4* __restrict__ W2, uint4* __restrict__ W2bf)
{
    const float4* in;
    uint4* out;
    int b = blockIdx.x;
    int which;
    if (b < 8192)      { in = A;  out = Abf;  which = 0; }
    else if (b < 9216) { in = W1; out = W1bf; which = 1; b -= 8192; }
    else               { in = W2; out = W2bf; which = 2; b -= 9216; }
    const int t = threadIdx.x;
    float4 v[8];
#pragma unroll
    for (int k = 0; k < 4; k++) {
        int i = b * 2048 + t * 2 + k * 512;
        v[2 * k]     = __ldcs(in + i);
        v[2 * k + 1] = __ldcs(in + i + 1);
    }
#pragma unroll
    for (int k = 0; k < 4; k++) {
        __nv_bfloat162 a0 = __floats2bfloat162_rn(v[2 * k].x,     v[2 * k].y);
        __nv_bfloat162 a1 = __floats2bfloat162_rn(v[2 * k].z,     v[2 * k].w);
        __nv_bfloat162 a2 = __floats2bfloat162_rn(v[2 * k + 1].x, v[2 * k + 1].y);
        __nv_bfloat162 a3 = __floats2bfloat162_rn(v[2 * k + 1].z, v[2 * k + 1].w);
        __stcs(out + b * 1024 + t + k * 256,
               make_uint4(*(uint32_t*)&a0, *(uint32_t*)&a1,
                          *(uint32_t*)&a2, *(uint32_t*)&a3));
    }

    if (which == 1) {
        float s = 0.f;
#pragma unroll
        for (int k = 0; k < 8; k++)
            s += v[k].x * v[k].x + v[k].y * v[k].y + v[k].z * v[k].z + v[k].w * v[k].w;
        s = block_reduce(s);
        if (t == 0) atomicAdd(&g_acc[2], sqrtf(s));
    } else if (which == 2) {
        __shared__ float srow[8];
        if (t < 8) srow[t] = 0.f;
        __syncthreads();
#pragma unroll
        for (int k = 0; k < 4; k++) {
            float p = v[2 * k].x * v[2 * k].x + v[2 * k].y * v[2 * k].y
                    + v[2 * k].z * v[2 * k].z + v[2 * k].w * v[2 * k].w
                    + v[2 * k + 1].x * v[2 * k + 1].x + v[2 * k + 1].y * v[2 * k + 1].y
                    + v[2 * k + 1].z * v[2 * k + 1].z + v[2 * k + 1].w * v[2 * k + 1].w;
#pragma unroll
            for (int o = 16; o > 0; o >>= 1) p += __shfl_xor_sync(0xffffffffu, p, o);
            if ((t & 31) == 0) atomicAdd(&srow[(t >> 7) + 2 * k], p);
        }
        __syncthreads();
        if (t < 8) atomicAdd(&g_acc[2], sqrtf(srow[t]));
    }
}

__device__ __forceinline__ float d2_bf8(uint4 x, uint4 y) {
    float s = 0.f;
    const uint32_t* xp = (const uint32_t*)&x;
    const uint32_t* yp = (const uint32_t*)&y;
#pragma unroll
    for (int qq = 0; qq < 4; qq++) {
        float2 a = __bfloat1622float2(*(const __nv_bfloat162*)&xp[qq]);
        float2 b = __bfloat1622float2(*(const __nv_bfloat162*)&yp[qq]);
        float d0 = a.x - b.x, d1 = a.y - b.y;
        s += d0 * d0 + d1 * d1;
    }
    return s;
}

// squared distance over 16 fp8 (e4m3) element pairs
__device__ __forceinline__ float d2_f8_16(uint4 x, uint4 y) {
    float s = 0.f;
    const unsigned short* xp = (const unsigned short*)&x;
    const unsigned short* yp = (const unsigned short*)&y;
#pragma unroll
    for (int qq = 0; qq < 8; qq++) {
        __half2_raw hx = __nv_cvt_fp8x2_to_halfraw2((__nv_fp8x2_storage_t)xp[qq], __NV_E4M3);
        __half2_raw hy = __nv_cvt_fp8x2_to_halfraw2((__nv_fp8x2_storage_t)yp[qq], __NV_E4M3);
        float2 fx = __half22float2(*(const __half2*)&hx);
        float2 fy = __half22float2(*(const __half2*)&hy);
        float d0 = fx.x - fy.x, d1 = fx.y - fy.y;
        s += d0 * d0 + d1 * d1;
    }
    return s;
}

__global__ void zero_kernel() {
    int i = blockIdx.x * blockDim.x + threadIdx.x;
    if (i < NN) { g_d2sq[i] = 0.f; g_mask[i] = 0; }
    if (i == 0) { g_acc[0] = 0.f; g_acc[1] = 0.f; g_acc[2] = 0.f; }
}

// mask build + bias norms (b1: block 32, b2: block 33)
__global__ void mask_bias_kernel(const int* __restrict__ edges,
                                 const int* __restrict__ labels,
                                 const float* __restrict__ b1,
                                 const float* __restrict__ b2) {
    int b = blockIdx.x;
    if (b < 32) {
        int e = b * 256 + threadIdx.x;
        if (labels[e] != 0) {
            g_mask[edges[2 * e + 0]] = 1;
            g_mask[edges[2 * e + 1]] = 1;
        }
    } else {
        const float* p = (b == 32) ? b1 : b2;
        int len = (b == 32) ? HD : NN;
        float s = 0.f;
        for (int c = threadIdx.x; c < len; c += 256) { float x = p[c]; s += x * x; }
        s = block_reduce(s);
        if (threadIdx.x == 0) atomicAdd(&g_acc[2], sqrtf(s));
    }
}

// edge losses; H2 now fp8 (half the read traffic)
__global__ void edge_loss_kernel(const int* __restrict__ edges,
                                 const int* __restrict__ labels) {
    int e  = blockIdx.x;
    int ni = edges[2 * e + 0];
    int nj = edges[2 * e + 1];
    int lab = labels[e];

    if (lab != 0) {
        const int t = threadIdx.x;
        // H1 distances (bf16, L2-resident)
        const uint4* hi1 = (const uint4*)(g_H1bf + (size_t)ni * HD);
        const uint4* hj1 = (const uint4*)(g_H1bf + (size_t)nj * HD);
        float s1 = 0.f;
        if (t < 128) s1 = d2_bf8(__ldca(hi1 + t), __ldca(hj1 + t));

        // H2 distances (fp8, DRAM): 8192 fp8 per row = 512 uint4 chunks
        const uint4* hi2 = (const uint4*)(g_H28 + (size_t)ni * NN);
        const uint4* hj2 = (const uint4*)(g_H28 + (size_t)nj * NN);
        uint4 xi[2], xj[2];
#pragma unroll
        for (int k = 0; k < 2; k++) {
            int c = t + k * 256;
            xi[k] = __ldcs(hi2 + c);
            xj[k] = __ldcs(hj2 + c);
        }
        float s2 = d2_f8_16(xi[0], xj[0]) + d2_f8_16(xi[1], xj[1]);

        s1 = block_reduce(s1);
        s2 = block_reduce(s2);
        if (t == 0) atomicAdd(&g_acc[0], sqrtf(s1) + sqrtf(s2));
    }
    if (threadIdx.x == 0) {
        float factor = (lab != 0) ? 10.f : 1.f;
        atomicAdd(&g_acc[1], factor * (sqrtf(g_d2sq[ni]) + sqrtf(g_d2sq[nj])));
    }
}

__global__ void finalize_kernel(float* out) {
    out[0] = g_acc[0] + g_acc[1] + g_acc[2] * (float)EE;
}

// ---------------- launch ----------------
extern "C" void kernel_launch(void* const* d_in, const int* in_sizes, int n_in,
                              void* d_out, int out_size) {
    const float* A      = (const float*)d_in[0];
    const float* W1     = (const float*)d_in[1];
    const float* b1     = (const float*)d_in[2];
    const float* W2     = (const float*)d_in[3];
    const float* b2     = (const float*)d_in[4];
    const int*   edges  = (const int*)d_in[5];
    const int*   labels = (const int*)d_in[6];
    float* out = (float*)d_out;

    __nv_bfloat16 *Abf, *W1bf, *W2bf, *H1bf;
    unsigned char *H28;
    float* d2sq;
    unsigned char* mask;
    cudaGetSymbolAddress((void**)&Abf,  g_Abf);
    cudaGetSymbolAddress((void**)&W1bf, g_W1bf);
    cudaGetSymbolAddress((void**)&W2bf, g_W2bf);
    cudaGetSymbolAddress((void**)&H1bf, g_H1bf);
    cudaGetSymbolAddress((void**)&H28,  g_H28);
    cudaGetSymbolAddress((void**)&d2sq, g_d2sq);
    cudaGetSymbolAddress((void**)&mask, g_mask);

    cudaFuncSetAttribute(gemm1_hmma,
                         cudaFuncAttributeMaxDynamicSharedMemorySize, G_SMEM);
    cudaFuncSetAttribute(gemm2_fused,
                         cudaFuncAttributeMaxDynamicSharedMemorySize, G_SMEM);

    zero_kernel<<<NN / 256, 256>>>();
    mask_bias_kernel<<<34, 256>>>(edges, labels, b1, b2);

    // merged fp32 -> bf16 conversions (+ W row-norm fold)
    convert_all<<<10240, 256>>>((const float4*)A,  (uint4*)Abf,
                                (const float4*)W1, (uint4*)W1bf,
                                (const float4*)W2, (uint4*)W2bf);

    // H1 = sigmoid(A @ W1^T + b1): M=8192, Nc=1024, K=8192
    gemm1_hmma<<<dim3(HD / 128, NN / 128), 256, G_SMEM>>>(Abf, W1bf, b1, H1bf, NN, HD);
    // H2 = sigmoid(H1 @ W2^T + b2) + fused residual, mask-gated fp8 stores
    gemm2_fused<<<dim3(NN / 128, NN / 128), 256, G_SMEM>>>(
        H1bf, W2bf, b2, H28, Abf, d2sq, mask, HD, NN);

    edge_loss_kernel<<<EE, 256>>>(edges, labels);
    finalize_kernel<<<1, 1>>>(out);
}

// round 16
// speedup vs baseline: 1.1020x; 1.0455x over previous
#include <cuda_runtime.h>
#include <cuda_fp16.h>
#include <cuda_fp8.h>
#include <cstdint>
#include <math.h>

#define NN 8192
#define HD 1024
#define EE 8192

// ---------------- scratch (device globals; allocation-free) ----------------
__device__ __half g_Ah[(size_t)NN * NN];    // 128 MB fp16 A
__device__ __half g_W1h[(size_t)HD * NN];   // 16 MB
__device__ __half g_W2h[(size_t)NN * HD];   // 16 MB
__device__ __half g_H1h[(size_t)NN * HD];   // 16 MB
__device__ unsigned char g_H28[(size_t)NN * NN];  // 64 MB fp8 H2
__device__ float g_d2sq[NN];
__device__ float g_acc[3];
__device__ unsigned char g_mask[NN];

// ---------------- PTX helpers ----------------
__device__ __forceinline__ uint32_t smem_u32(const void* p) {
    uint32_t a;
    asm("{ .reg .u64 t; cvta.to.shared.u64 t, %1; cvt.u32.u64 %0, t; }" : "=r"(a) : "l"(p));
    return a;
}

#define CP_ASYNC16(dst, src) \
    asm volatile("cp.async.cg.shared.global [%0], [%1], 16;" :: "r"(dst), "l"(src) : "memory")
#define CP_COMMIT() asm volatile("cp.async.commit_group;" ::: "memory")
template <int N>
__device__ __forceinline__ void cp_wait() {
    asm volatile("cp.async.wait_group %0;" :: "n"(N) : "memory");
}

__device__ __forceinline__ void ldsm4(uint32_t* r, uint32_t addr) {
    asm volatile("ldmatrix.sync.aligned.m8n8.x4.shared.b16 {%0,%1,%2,%3}, [%4];"
                 : "=r"(r[0]), "=r"(r[1]), "=r"(r[2]), "=r"(r[3]) : "r"(addr));
}

// fp16 MMA with f16 accumulator: C(2 regs of half2) += A(4) * B(2)
__device__ __forceinline__ void mma_fp16(uint32_t* c, const uint32_t* a,
                                         uint32_t b0, uint32_t b1) {
    asm volatile(
        "mma.sync.aligned.m16n8k16.row.col.f16.f16.f16.f16 "
        "{%0,%1}, {%2,%3,%4,%5}, {%6,%7}, {%0,%1};"
        : "+r"(c[0]), "+r"(c[1])
        : "r"(a[0]), "r"(a[1]), "r"(a[2]), "r"(a[3]), "r"(b0), "r"(b1));
}

__device__ __forceinline__ uint32_t sw128(uint32_t off) {
    return off ^ ((off >> 3) & 0x70);
}

// shared stage loader: A tile 128x64 fp16 + B tile 128x64 fp16, SW128 swizzled
__device__ __forceinline__ void load_stage(
    const __half* __restrict__ Ah, const __half* __restrict__ Bh,
    int K, int bm0, int bn0, int kt, uint32_t stageBase, int tid)
{
#pragma unroll
    for (int r = 0; r < 4; r++) {
        int idx = tid + r * 256;
        int row = idx >> 3, ck = idx & 7;
        uint32_t sw = sw128((uint32_t)(row * 128 + ck * 16));
        const void* srcA = (const char*)(Ah + (size_t)(bm0 + row) * K + kt) + ck * 16;
        CP_ASYNC16(stageBase + sw, srcA);
        const void* srcB = (const char*)(Bh + (size_t)(bn0 + row) * K + kt) + ck * 16;
        CP_ASYNC16(stageBase + 16384 + sw, srcB);
    }
    CP_COMMIT();
}

#define STAGE_BYTES 32768
#define G_SMEM (2 * STAGE_BYTES)

__device__ __forceinline__ float2 h2f(uint32_t u) {
    return __half22float2(*(const __half2*)&u);
}

// =======================================================================
// GEMM1: fp16 in / f16 acc, 2-stage, 2 CTAs/SM
// =======================================================================
__global__ void __launch_bounds__(256, 2)
gemm1_hmma(const __half* __restrict__ Ah,
           const __half* __restrict__ Bh,
           const float* __restrict__ bias,
           __half* __restrict__ Hout,
           int K, int Nc)
{
    extern __shared__ __align__(1024) char smem[];
    const uint32_t sb0 = smem_u32(smem);
    const int tid = threadIdx.x;
    const int wid = tid >> 5, lid = tid & 31;
    const int warp_m = wid >> 2;
    const int warp_n = wid & 3;
    const int bm0 = blockIdx.y * 128;
    const int bn0 = blockIdx.x * 128;

    const int q  = lid >> 3;
    const int r8 = lid & 7;
    const int arowb = warp_m * 64 + (q & 1) * 8 + r8;
    const int browb = warp_n * 32 + (q & 1) * 8 + r8;
    const uint32_t kq   = (uint32_t)((q >> 1) * 16);
    const uint32_t axor = (uint32_t)((arowb & 7) << 4);
    const uint32_t bxor = (uint32_t)((browb & 7) << 4);

    uint32_t acc[4][4][2];
#pragma unroll
    for (int i = 0; i < 4; i++)
#pragma unroll
        for (int j = 0; j < 4; j++) { acc[i][j][0] = 0u; acc[i][j][1] = 0u; }

    const int T = K >> 6;

    load_stage(Ah, Bh, K, bm0, bn0, 0, sb0, tid);

    for (int i = 0; i < T; i++) {
        if (i + 1 < T)
            load_stage(Ah, Bh, K, bm0, bn0, (i + 1) * 64,
                       sb0 + (uint32_t)((i + 1) & 1) * STAGE_BYTES, tid);
        if (i + 1 < T) cp_wait<1>(); else cp_wait<0>();
        __syncthreads();

        const uint32_t Ab = sb0 + (uint32_t)(i & 1) * STAGE_BYTES;
        const uint32_t Bb = Ab + 16384;

#pragma unroll
        for (int s = 0; s < 4; s++) {
            const uint32_t koff = (uint32_t)(s * 32) | kq;
            uint32_t a[4][4], bfr[2][4];
#pragma unroll
            for (int mt = 0; mt < 4; mt++)
                ldsm4(a[mt], Ab + (uint32_t)(arowb + mt * 16) * 128 + (koff ^ axor));
#pragma unroll
            for (int bt = 0; bt < 2; bt++)
                ldsm4(bfr[bt], Bb + (uint32_t)(browb + bt * 16) * 128 + (koff ^ bxor));
#pragma unroll
            for (int mt = 0; mt < 4; mt++)
#pragma unroll
                for (int nt = 0; nt < 4; nt++)
                    mma_fp16(acc[mt][nt], a[mt], bfr[nt >> 1][nt & 1], bfr[nt >> 1][(nt & 1) + 2]);
        }
        __syncthreads();
    }

    const int rr = lid >> 2;
    const int cc = (lid & 3) * 2;
#pragma unroll
    for (int nt = 0; nt < 4; nt++) {
        const int col = bn0 + warp_n * 32 + nt * 8 + cc;
        const float bb0 = bias[col], bb1 = bias[col + 1];
#pragma unroll
        for (int mt = 0; mt < 4; mt++) {
            const int row0 = bm0 + warp_m * 64 + mt * 16 + rr;
            float2 c01 = h2f(acc[mt][nt][0]);
            float2 c23 = h2f(acc[mt][nt][1]);
            float s0 = 1.f / (1.f + __expf(-(c01.x + bb0)));
            float s1 = 1.f / (1.f + __expf(-(c01.y + bb1)));
            float s2 = 1.f / (1.f + __expf(-(c23.x + bb0)));
            float s3 = 1.f / (1.f + __expf(-(c23.y + bb1)));
            __half2 h01 = __float22half2_rn(make_float2(s0, s1));
            __half2 h23 = __float22half2_rn(make_float2(s2, s3));
            *(uint32_t*)(Hout + (size_t)row0 * Nc + col)       = *(uint32_t*)&h01;
            *(uint32_t*)(Hout + (size_t)(row0 + 8) * Nc + col) = *(uint32_t*)&h23;
        }
    }
}

// =======================================================================
// GEMM2: fp16/f16-acc, fused residual (vs fp16 A) + mask-gated fp8 stores
// =======================================================================
__global__ void __launch_bounds__(256, 2)
gemm2_fused(const __half* __restrict__ Ah,
            const __half* __restrict__ Bh,
            const float* __restrict__ bias,
            unsigned char* __restrict__ Hout8,
            const __half* __restrict__ Aref,
            float* __restrict__ d2sq,
            const unsigned char* __restrict__ mask,
            int K, int Nc)
{
    extern __shared__ __align__(1024) char smem[];
    const uint32_t sb0 = smem_u32(smem);
    const int tid = threadIdx.x;
    const int wid = tid >> 5, lid = tid & 31;
    const int warp_m = wid >> 2;
    const int warp_n = wid & 3;
    const int bm0 = blockIdx.y * 128;
    const int bn0 = blockIdx.x * 128;

    const int q  = lid >> 3;
    const int r8 = lid & 7;
    const int arowb = warp_m * 64 + (q & 1) * 8 + r8;
    const int browb = warp_n * 32 + (q & 1) * 8 + r8;
    const uint32_t kq   = (uint32_t)((q >> 1) * 16);
    const uint32_t axor = (uint32_t)((arowb & 7) << 4);
    const uint32_t bxor = (uint32_t)((browb & 7) << 4);

    uint32_t acc[4][4][2];
#pragma unroll
    for (int i = 0; i < 4; i++)
#pragma unroll
        for (int j = 0; j < 4; j++) { acc[i][j][0] = 0u; acc[i][j][1] = 0u; }

    const int T = K >> 6;   // 16

    load_stage(Ah, Bh, K, bm0, bn0, 0, sb0, tid);

    for (int i = 0; i < T; i++) {
        if (i + 1 < T)
            load_stage(Ah, Bh, K, bm0, bn0, (i + 1) * 64,
                       sb0 + (uint32_t)((i + 1) & 1) * STAGE_BYTES, tid);
        if (i + 1 < T) cp_wait<1>(); else cp_wait<0>();
        __syncthreads();

        const uint32_t Ab = sb0 + (uint32_t)(i & 1) * STAGE_BYTES;
        const uint32_t Bb = Ab + 16384;

#pragma unroll
        for (int s = 0; s < 4; s++) {
            const uint32_t koff = (uint32_t)(s * 32) | kq;
            uint32_t a[4][4], bfr[2][4];
#pragma unroll
            for (int mt = 0; mt < 4; mt++)
                ldsm4(a[mt], Ab + (uint32_t)(arowb + mt * 16) * 128 + (koff ^ axor));
#pragma unroll
            for (int bt = 0; bt < 2; bt++)
                ldsm4(bfr[bt], Bb + (uint32_t)(browb + bt * 16) * 128 + (koff ^ bxor));
#pragma unroll
            for (int mt = 0; mt < 4; mt++)
#pragma unroll
                for (int nt = 0; nt < 4; nt++)
                    mma_fp16(acc[mt][nt], a[mt], bfr[nt >> 1][nt & 1], bfr[nt >> 1][(nt & 1) + 2]);
        }
        __syncthreads();
    }

    const int rr = lid >> 2;
    const int cc = (lid & 3) * 2;
    float sum0[4] = {0.f, 0.f, 0.f, 0.f};
    float sum8[4] = {0.f, 0.f, 0.f, 0.f};
    bool m0[4], m8[4];
#pragma unroll
    for (int mt = 0; mt < 4; mt++) {
        const int row0 = bm0 + warp_m * 64 + mt * 16 + rr;
        m0[mt] = mask[row0] != 0;
        m8[mt] = mask[row0 + 8] != 0;
    }

#pragma unroll
    for (int nt = 0; nt < 4; nt++) {
        const int col = bn0 + warp_n * 32 + nt * 8 + cc;
        const float bb0 = bias[col], bb1 = bias[col + 1];
#pragma unroll
        for (int mt = 0; mt < 4; mt++) {
            const int row0 = bm0 + warp_m * 64 + mt * 16 + rr;
            float2 c01 = h2f(acc[mt][nt][0]);
            float2 c23 = h2f(acc[mt][nt][1]);
            float s0 = 1.f / (1.f + __expf(-(c01.x + bb0)));
            float s1 = 1.f / (1.f + __expf(-(c01.y + bb1)));
            float s2 = 1.f / (1.f + __expf(-(c23.x + bb0)));
            float s3 = 1.f / (1.f + __expf(-(c23.y + bb1)));
            float2 a01 = h2f(__ldcs((const uint32_t*)(Aref + (size_t)row0 * Nc + col)));
            float2 a23 = h2f(__ldcs((const uint32_t*)(Aref + (size_t)(row0 + 8) * Nc + col)));
            float d0 = a01.x - s0, d1 = a01.y - s1;
            float d2v = a23.x - s2, d3 = a23.y - s3;
            sum0[mt] += d0 * d0 + d1 * d1;
            sum8[mt] += d2v * d2v + d3 * d3;
            if (m0[mt]) {
                __nv_fp8x2_storage_t f01 = __nv_cvt_float2_to_fp8x2(
                    make_float2(s0, s1), __NV_SATFINITE, __NV_E4M3);
                *(unsigned short*)(Hout8 + (size_t)row0 * Nc + col) = (unsigned short)f01;
            }
            if (m8[mt]) {
                __nv_fp8x2_storage_t f23 = __nv_cvt_float2_to_fp8x2(
                    make_float2(s2, s3), __NV_SATFINITE, __NV_E4M3);
                *(unsigned short*)(Hout8 + (size_t)(row0 + 8) * Nc + col) = (unsigned short)f23;
            }
        }
    }

#pragma unroll
    for (int mt = 0; mt < 4; mt++) {
        float s0v = sum0[mt], s8v = sum8[mt];
        s0v += __shfl_xor_sync(0xffffffffu, s0v, 1);
        s0v += __shfl_xor_sync(0xffffffffu, s0v, 2);
        s8v += __shfl_xor_sync(0xffffffffu, s8v, 1);
        s8v += __shfl_xor_sync(0xffffffffu, s8v, 2);
        if ((lid & 3) == 0) {
            const int row0 = bm0 + warp_m * 64 + mt * 16 + rr;
            atomicAdd(&d2sq[row0], s0v);
            atomicAdd(&d2sq[row0 + 8], s8v);
        }
    }
}

// ---------------- block reduction (256 threads) ----------------
__device__ __forceinline__ float block_reduce(float v) {
    __shared__ float sh[8];
    __syncthreads();
    int lane = threadIdx.x & 31;
    int w    = threadIdx.x >> 5;
#pragma unroll
    for (int o = 16; o > 0; o >>= 1) v += __shfl_down_sync(0xffffffffu, v, o);
    if (lane == 0) sh[w] = v;
    __syncthreads();
    if (w == 0) {
        v = (lane < 8) ? sh[lane] : 0.f;
#pragma unroll
        for (int o = 4; o > 0; o >>= 1) v += __shfl_down_sync(0xffffffffu, v, o);
    }
    return v;
}

// ---------------- merged fp32 -> fp16 conversion + W row-norm fold ----------
__global__ void convert_all(const float4* __restrict__ A, uint4* __restrict__ Ah,
                            const float4* __restrict__ W1, uint4* __restrict__ W1h,
                            const float4* __restrict__ W2, uint4* __restrict__ W2h)
{
    const float4* in;
    uint4* out;
    int b = blockIdx.x;
    int which;
    if (b < 8192)      { in = A;  out = Ah;  which = 0; }
    else if (b < 9216) { in = W1; out = W1h; which = 1; b -= 8192; }
    else               { in = W2; out = W2h; which = 2; b -= 9216; }
    const int t = threadIdx.x;
    float4 v[8];
#pragma unroll
    for (int k = 0; k < 4; k++) {
        int i = b * 2048 + t * 2 + k * 512;
        v[2 * k]     = __ldcs(in + i);
        v[2 * k + 1] = __ldcs(in + i + 1);
    }
#pragma unroll
    for (int k = 0; k < 4; k++) {
        __half2 a0 = __float22half2_rn(make_float2(v[2 * k].x,     v[2 * k].y));
        __half2 a1 = __float22half2_rn(make_float2(v[2 * k].z,     v[2 * k].w));
        __half2 a2 = __float22half2_rn(make_float2(v[2 * k + 1].x, v[2 * k + 1].y));
        __half2 a3 = __float22half2_rn(make_float2(v[2 * k + 1].z, v[2 * k + 1].w));
        __stcs(out + b * 1024 + t + k * 256,
               make_uint4(*(uint32_t*)&a0, *(uint32_t*)&a1,
                          *(uint32_t*)&a2, *(uint32_t*)&a3));
    }

    if (which == 1) {
        float s = 0.f;
#pragma unroll
        for (int k = 0; k < 8; k++)
            s += v[k].x * v[k].x + v[k].y * v[k].y + v[k].z * v[k].z + v[k].w * v[k].w;
        s = block_reduce(s);
        if (t == 0) atomicAdd(&g_acc[2], sqrtf(s));
    } else if (which == 2) {
        __shared__ float srow[8];
        if (t < 8) srow[t] = 0.f;
        __syncthreads();
#pragma unroll
        for (int k = 0; k < 4; k++) {
            float p = v[2 * k].x * v[2 * k].x + v[2 * k].y * v[2 * k].y
                    + v[2 * k].z * v[2 * k].z + v[2 * k].w * v[2 * k].w
                    + v[2 * k + 1].x * v[2 * k + 1].x + v[2 * k + 1].y * v[2 * k + 1].y
                    + v[2 * k + 1].z * v[2 * k + 1].z + v[2 * k + 1].w * v[2 * k + 1].w;
#pragma unroll
            for (int o = 16; o > 0; o >>= 1) p += __shfl_xor_sync(0xffffffffu, p, o);
            if ((t & 31) == 0) atomicAdd(&srow[(t >> 7) + 2 * k], p);
        }
        __syncthreads();
        if (t < 8) atomicAdd(&g_acc[2], sqrtf(srow[t]));
    }
}

// squared distance over 8 fp16 element pairs
__device__ __forceinline__ float d2_h8(uint4 x, uint4 y) {
    float s = 0.f;
    const uint32_t* xp = (const uint32_t*)&x;
    const uint32_t* yp = (const uint32_t*)&y;
#pragma unroll
    for (int qq = 0; qq < 4; qq++) {
        float2 a = __half22float2(*(const __half2*)&xp[qq]);
        float2 b = __half22float2(*(const __half2*)&yp[qq]);
        float d0 = a.x - b.x, d1 = a.y - b.y;
        s += d0 * d0 + d1 * d1;
    }
    return s;
}

// squared distance over 16 fp8 (e4m3) element pairs
__device__ __forceinline__ float d2_f8_16(uint4 x, uint4 y) {
    float s = 0.f;
    const unsigned short* xp = (const unsigned short*)&x;
    const unsigned short* yp = (const unsigned short*)&y;
#pragma unroll
    for (int qq = 0; qq < 8; qq++) {
        __half2_raw hx = __nv_cvt_fp8x2_to_halfraw2((__nv_fp8x2_storage_t)xp[qq], __NV_E4M3);
        __half2_raw hy = __nv_cvt_fp8x2_to_halfraw2((__nv_fp8x2_storage_t)yp[qq], __NV_E4M3);
        float2 fx = __half22float2(*(const __half2*)&hx);
        float2 fy = __half22float2(*(const __half2*)&hy);
        float d0 = fx.x - fy.x, d1 = fx.y - fy.y;
        s += d0 * d0 + d1 * d1;
    }
    return s;
}

__global__ void zero_kernel() {
    int i = blockIdx.x * blockDim.x + threadIdx.x;
    if (i < NN) { g_d2sq[i] = 0.f; g_mask[i] = 0; }
    if (i == 0) { g_acc[0] = 0.f; g_acc[1] = 0.f; g_acc[2] = 0.f; }
}

// mask build + bias norms (b1: block 32, b2: block 33)
__global__ void mask_bias_kernel(const int* __restrict__ edges,
                                 const int* __restrict__ labels,
                                 const float* __restrict__ b1,
                                 const float* __restrict__ b2) {
    int b = blockIdx.x;
    if (b < 32) {
        int e = b * 256 + threadIdx.x;
        if (labels[e] != 0) {
            g_mask[edges[2 * e + 0]] = 1;
            g_mask[edges[2 * e + 1]] = 1;
        }
    } else {
        const float* p = (b == 32) ? b1 : b2;
        int len = (b == 32) ? HD : NN;
        float s = 0.f;
        for (int c = threadIdx.x; c < len; c += 256) { float x = p[c]; s += x * x; }
        s = block_reduce(s);
        if (threadIdx.x == 0) atomicAdd(&g_acc[2], sqrtf(s));
    }
}

// edge losses; H1 fp16, H2 fp8
__global__ void edge_loss_kernel(const int* __restrict__ edges,
                                 const int* __restrict__ labels) {
    int e  = blockIdx.x;
    int ni = edges[2 * e + 0];
    int nj = edges[2 * e + 1];
    int lab = labels[e];

    if (lab != 0) {
        const int t = threadIdx.x;
        const uint4* hi1 = (const uint4*)(g_H1h + (size_t)ni * HD);
        const uint4* hj1 = (const uint4*)(g_H1h + (size_t)nj * HD);
        float s1 = 0.f;
        if (t < 128) s1 = d2_h8(__ldca(hi1 + t), __ldca(hj1 + t));

        const uint4* hi2 = (const uint4*)(g_H28 + (size_t)ni * NN);
        const uint4* hj2 = (const uint4*)(g_H28 + (size_t)nj * NN);
        uint4 xi[2], xj[2];
#pragma unroll
        for (int k = 0; k < 2; k++) {
            int c = t + k * 256;
            xi[k] = __ldcs(hi2 + c);
            xj[k] = __ldcs(hj2 + c);
        }
        float s2 = d2_f8_16(xi[0], xj[0]) + d2_f8_16(xi[1], xj[1]);

        s1 = block_reduce(s1);
        s2 = block_reduce(s2);
        if (t == 0) atomicAdd(&g_acc[0], sqrtf(s1) + sqrtf(s2));
    }
    if (threadIdx.x == 0) {
        float factor = (lab != 0) ? 10.f : 1.f;
        atomicAdd(&g_acc[1], factor * (sqrtf(g_d2sq[ni]) + sqrtf(g_d2sq[nj])));
    }
}

__global__ void finalize_kernel(float* out) {
    out[0] = g_acc[0] + g_acc[1] + g_acc[2] * (float)EE;
}

// ---------------- launch ----------------
extern "C" void kernel_launch(void* const* d_in, const int* in_sizes, int n_in,
                              void* d_out, int out_size) {
    const float* A      = (const float*)d_in[0];
    const float* W1     = (const float*)d_in[1];
    const float* b1     = (const float*)d_in[2];
    const float* W2     = (const float*)d_in[3];
    const float* b2     = (const float*)d_in[4];
    const int*   edges  = (const int*)d_in[5];
    const int*   labels = (const int*)d_in[6];
    float* out = (float*)d_out;

    __half *Ah, *W1h, *W2h, *H1h;
    unsigned char *H28;
    float* d2sq;
    unsigned char* mask;
    cudaGetSymbolAddress((void**)&Ah,   g_Ah);
    cudaGetSymbolAddress((void**)&W1h,  g_W1h);
    cudaGetSymbolAddress((void**)&W2h,  g_W2h);
    cudaGetSymbolAddress((void**)&H1h,  g_H1h);
    cudaGetSymbolAddress((void**)&H28,  g_H28);
    cudaGetSymbolAddress((void**)&d2sq, g_d2sq);
    cudaGetSymbolAddress((void**)&mask, g_mask);

    cudaFuncSetAttribute(gemm1_hmma,
                         cudaFuncAttributeMaxDynamicSharedMemorySize, G_SMEM);
    cudaFuncSetAttribute(gemm2_fused,
                         cudaFuncAttributeMaxDynamicSharedMemorySize, G_SMEM);

    zero_kernel<<<NN / 256, 256>>>();
    mask_bias_kernel<<<34, 256>>>(edges, labels, b1, b2);

    // merged fp32 -> fp16 conversions (+ W row-norm fold)
    convert_all<<<10240, 256>>>((const float4*)A,  (uint4*)Ah,
                                (const float4*)W1, (uint4*)W1h,
                                (const float4*)W2, (uint4*)W2h);

    // H1 = sigmoid(A @ W1^T + b1): M=8192, Nc=1024, K=8192
    gemm1_hmma<<<dim3(HD / 128, NN / 128), 256, G_SMEM>>>(Ah, W1h, b1, H1h, NN, HD);
    // H2 = sigmoid(H1 @ W2^T + b2) + fused residual, mask-gated fp8 stores
    gemm2_fused<<<dim3(NN / 128, NN / 128), 256, G_SMEM>>>(
        H1h, W2h, b2, H28, Ah, d2sq, mask, HD, NN);

    edge_loss_kernel<<<EE, 256>>>(edges, labels);
    finalize_kernel<<<1, 1>>>(out);
}

// round 17
// speedup vs baseline: 1.1146x; 1.0114x over previous
#include <cuda_runtime.h>
#include <cuda_fp16.h>
#include <cuda_fp8.h>
#include <cstdint>
#include <math.h>

#define NN 8192
#define HD 1024
#define EE 8192

// ---------------- scratch (device globals; allocation-free) ----------------
__device__ __half g_Ah[(size_t)NN * NN];    // 128 MB fp16 A
__device__ __half g_W1h[(size_t)HD * NN];   // 16 MB
__device__ __half g_W2h[(size_t)NN * HD];   // 16 MB
__device__ __half g_H1h[(size_t)NN * HD];   // 16 MB
__device__ unsigned char g_H28[(size_t)NN * NN];  // 64 MB fp8 H2
__device__ float g_d2sq[NN];
__device__ float g_acc[3];
__device__ unsigned char g_mask[NN];

// ---------------- PTX helpers ----------------
__device__ __forceinline__ uint32_t smem_u32(const void* p) {
    uint32_t a;
    asm("{ .reg .u64 t; cvta.to.shared.u64 t, %1; cvt.u32.u64 %0, t; }" : "=r"(a) : "l"(p));
    return a;
}

#define CP_ASYNC16(dst, src) \
    asm volatile("cp.async.cg.shared.global [%0], [%1], 16;" :: "r"(dst), "l"(src) : "memory")
#define CP_COMMIT() asm volatile("cp.async.commit_group;" ::: "memory")
template <int N>
__device__ __forceinline__ void cp_wait() {
    asm volatile("cp.async.wait_group %0;" :: "n"(N) : "memory");
}

__device__ __forceinline__ void ldsm4(uint32_t* r, uint32_t addr) {
    asm volatile("ldmatrix.sync.aligned.m8n8.x4.shared.b16 {%0,%1,%2,%3}, [%4];"
                 : "=r"(r[0]), "=r"(r[1]), "=r"(r[2]), "=r"(r[3]) : "r"(addr));
}

// fp16 MMA with f16 accumulator
__device__ __forceinline__ void mma_fp16(uint32_t* c, const uint32_t* a,
                                         uint32_t b0, uint32_t b1) {
    asm volatile(
        "mma.sync.aligned.m16n8k16.row.col.f16.f16.f16.f16 "
        "{%0,%1}, {%2,%3,%4,%5}, {%6,%7}, {%0,%1};"
        : "+r"(c[0]), "+r"(c[1])
        : "r"(a[0]), "r"(a[1]), "r"(a[2]), "r"(a[3]), "r"(b0), "r"(b1));
}

__device__ __forceinline__ uint32_t sw128(uint32_t off) {
    return off ^ ((off >> 3) & 0x70);
}

#define STAGE_BYTES 32768
#define G_SMEM (2 * STAGE_BYTES)

__device__ __forceinline__ float2 h2f(uint32_t u) {
    return __half22float2(*(const __half2*)&u);
}

// =======================================================================
// Shared GEMM mainloop body (pointer-incremental loads, precomputed
// ldsm address constants). Produces per-thread f16 accumulators.
// =======================================================================
struct GemmCtx {
    const char* srcA[4];
    const char* srcB[4];
    uint32_t dstsw[4];       // swizzled smem offsets for this thread's rows
    uint32_t aAddr[4];       // Ab-relative ldsm row offsets (mt)
    uint32_t bAddr[2];       // Bb-relative ldsm row offsets (bt)
    uint32_t koffA[4];       // per-s (koff ^ axor)
    uint32_t koffB[4];       // per-s (koff ^ bxor)
};

__device__ __forceinline__ void gemm_setup(
    GemmCtx& cx, const __half* Ah, const __half* Bh,
    int K, int bm0, int bn0, int tid, int lid, int warp_m, int warp_n)
{
#pragma unroll
    for (int r = 0; r < 4; r++) {
        int idx = tid + r * 256;
        int row = idx >> 3, ck = idx & 7;
        cx.dstsw[r] = sw128((uint32_t)(row * 128 + ck * 16));
        cx.srcA[r] = (const char*)(Ah + (size_t)(bm0 + row) * K) + ck * 16;
        cx.srcB[r] = (const char*)(Bh + (size_t)(bn0 + row) * K) + ck * 16;
    }
    const int q  = lid >> 3;
    const int r8 = lid & 7;
    const int arowb = warp_m * 64 + (q & 1) * 8 + r8;
    const int browb = warp_n * 32 + (q & 1) * 8 + r8;
    const uint32_t kq   = (uint32_t)((q >> 1) * 16);
    const uint32_t axor = (uint32_t)((arowb & 7) << 4);
    const uint32_t bxor = (uint32_t)((browb & 7) << 4);
#pragma unroll
    for (int mt = 0; mt < 4; mt++) cx.aAddr[mt] = (uint32_t)(arowb + mt * 16) * 128;
#pragma unroll
    for (int bt = 0; bt < 2; bt++) cx.bAddr[bt] = (uint32_t)(browb + bt * 16) * 128;
#pragma unroll
    for (int s = 0; s < 4; s++) {
        uint32_t koff = (uint32_t)(s * 32) | kq;
        cx.koffA[s] = koff ^ axor;
        cx.koffB[s] = koff ^ bxor;
    }
}

__device__ __forceinline__ void gemm_load(const GemmCtx& cx, uint32_t stageBase,
                                          uint32_t byteOff) {
#pragma unroll
    for (int r = 0; r < 4; r++) {
        CP_ASYNC16(stageBase + cx.dstsw[r], cx.srcA[r] + byteOff);
        CP_ASYNC16(stageBase + 16384 + cx.dstsw[r], cx.srcB[r] + byteOff);
    }
    CP_COMMIT();
}

__device__ __forceinline__ void gemm_mainloop(
    const GemmCtx& cx, uint32_t sb0, int T, uint32_t acc[4][4][2])
{
    gemm_load(cx, sb0, 0);
    for (int i = 0; i < T; i++) {
        if (i + 1 < T)
            gemm_load(cx, sb0 + (uint32_t)((i + 1) & 1) * STAGE_BYTES,
                      (uint32_t)(i + 1) * 128);
        if (i + 1 < T) cp_wait<1>(); else cp_wait<0>();
        __syncthreads();

        const uint32_t Ab = sb0 + (uint32_t)(i & 1) * STAGE_BYTES;
        const uint32_t Bb = Ab + 16384;

#pragma unroll
        for (int s = 0; s < 4; s++) {
            uint32_t a[4][4], bfr[2][4];
#pragma unroll
            for (int mt = 0; mt < 4; mt++)
                ldsm4(a[mt], Ab + cx.aAddr[mt] + cx.koffA[s]);
#pragma unroll
            for (int bt = 0; bt < 2; bt++)
                ldsm4(bfr[bt], Bb + cx.bAddr[bt] + cx.koffB[s]);
#pragma unroll
            for (int mt = 0; mt < 4; mt++)
#pragma unroll
                for (int nt = 0; nt < 4; nt++)
                    mma_fp16(acc[mt][nt], a[mt],
                             bfr[nt >> 1][nt & 1], bfr[nt >> 1][(nt & 1) + 2]);
        }
        __syncthreads();
    }
}

// =======================================================================
// GEMM1: fp16 / f16-acc, 2-stage, 2 CTAs/SM, incremental addressing
// =======================================================================
__global__ void __launch_bounds__(256, 2)
gemm1_hmma(const __half* __restrict__ Ah,
           const __half* __restrict__ Bh,
           const float* __restrict__ bias,
           __half* __restrict__ Hout,
           int K, int Nc)
{
    extern __shared__ __align__(1024) char smem[];
    const uint32_t sb0 = smem_u32(smem);
    const int tid = threadIdx.x;
    const int wid = tid >> 5, lid = tid & 31;
    const int warp_m = wid >> 2;
    const int warp_n = wid & 3;
    const int bm0 = blockIdx.y * 128;
    const int bn0 = blockIdx.x * 128;

    GemmCtx cx;
    gemm_setup(cx, Ah, Bh, K, bm0, bn0, tid, lid, warp_m, warp_n);

    uint32_t acc[4][4][2];
#pragma unroll
    for (int i = 0; i < 4; i++)
#pragma unroll
        for (int j = 0; j < 4; j++) { acc[i][j][0] = 0u; acc[i][j][1] = 0u; }

    gemm_mainloop(cx, sb0, K >> 6, acc);

    const int rr = lid >> 2;
    const int cc = (lid & 3) * 2;
#pragma unroll
    for (int nt = 0; nt < 4; nt++) {
        const int col = bn0 + warp_n * 32 + nt * 8 + cc;
        const float bb0 = bias[col], bb1 = bias[col + 1];
#pragma unroll
        for (int mt = 0; mt < 4; mt++) {
            const int row0 = bm0 + warp_m * 64 + mt * 16 + rr;
            float2 c01 = h2f(acc[mt][nt][0]);
            float2 c23 = h2f(acc[mt][nt][1]);
            float s0 = 1.f / (1.f + __expf(-(c01.x + bb0)));
            float s1 = 1.f / (1.f + __expf(-(c01.y + bb1)));
            float s2 = 1.f / (1.f + __expf(-(c23.x + bb0)));
            float s3 = 1.f / (1.f + __expf(-(c23.y + bb1)));
            __half2 h01 = __float22half2_rn(make_float2(s0, s1));
            __half2 h23 = __float22half2_rn(make_float2(s2, s3));
            *(uint32_t*)(Hout + (size_t)row0 * Nc + col)       = *(uint32_t*)&h01;
            *(uint32_t*)(Hout + (size_t)(row0 + 8) * Nc + col) = *(uint32_t*)&h23;
        }
    }
}

// =======================================================================
// GEMM2: fp16/f16-acc, fused residual + mask-gated fp8 stores
// =======================================================================
__global__ void __launch_bounds__(256, 2)
gemm2_fused(const __half* __restrict__ Ah,
            const __half* __restrict__ Bh,
            const float* __restrict__ bias,
            unsigned char* __restrict__ Hout8,
            const __half* __restrict__ Aref,
            float* __restrict__ d2sq,
            const unsigned char* __restrict__ mask,
            int K, int Nc)
{
    extern __shared__ __align__(1024) char smem[];
    const uint32_t sb0 = smem_u32(smem);
    const int tid = threadIdx.x;
    const int wid = tid >> 5, lid = tid & 31;
    const int warp_m = wid >> 2;
    const int warp_n = wid & 3;
    const int bm0 = blockIdx.y * 128;
    const int bn0 = blockIdx.x * 128;

    GemmCtx cx;
    gemm_setup(cx, Ah, Bh, K, bm0, bn0, tid, lid, warp_m, warp_n);

    uint32_t acc[4][4][2];
#pragma unroll
    for (int i = 0; i < 4; i++)
#pragma unroll
        for (int j = 0; j < 4; j++) { acc[i][j][0] = 0u; acc[i][j][1] = 0u; }

    gemm_mainloop(cx, sb0, K >> 6, acc);

    const int rr = lid >> 2;
    const int cc = (lid & 3) * 2;
    float sum0[4] = {0.f, 0.f, 0.f, 0.f};
    float sum8[4] = {0.f, 0.f, 0.f, 0.f};
    bool m0[4], m8[4];
#pragma unroll
    for (int mt = 0; mt < 4; mt++) {
        const int row0 = bm0 + warp_m * 64 + mt * 16 + rr;
        m0[mt] = mask[row0] != 0;
        m8[mt] = mask[row0 + 8] != 0;
    }

#pragma unroll
    for (int nt = 0; nt < 4; nt++) {
        const int col = bn0 + warp_n * 32 + nt * 8 + cc;
        const float bb0 = bias[col], bb1 = bias[col + 1];
#pragma unroll
        for (int mt = 0; mt < 4; mt++) {
            const int row0 = bm0 + warp_m * 64 + mt * 16 + rr;
            float2 c01 = h2f(acc[mt][nt][0]);
            float2 c23 = h2f(acc[mt][nt][1]);
            float s0 = 1.f / (1.f + __expf(-(c01.x + bb0)));
            float s1 = 1.f / (1.f + __expf(-(c01.y + bb1)));
            float s2 = 1.f / (1.f + __expf(-(c23.x + bb0)));
            float s3 = 1.f / (1.f + __expf(-(c23.y + bb1)));
            float2 a01 = h2f(__ldcs((const uint32_t*)(Aref + (size_t)row0 * Nc + col)));
            float2 a23 = h2f(__ldcs((const uint32_t*)(Aref + (size_t)(row0 + 8) * Nc + col)));
            float d0 = a01.x - s0, d1 = a01.y - s1;
            float d2v = a23.x - s2, d3 = a23.y - s3;
            sum0[mt] += d0 * d0 + d1 * d1;
            sum8[mt] += d2v * d2v + d3 * d3;
            if (m0[mt]) {
                __nv_fp8x2_storage_t f01 = __nv_cvt_float2_to_fp8x2(
                    make_float2(s0, s1), __NV_SATFINITE, __NV_E4M3);
                *(unsigned short*)(Hout8 + (size_t)row0 * Nc + col) = (unsigned short)f01;
            }
            if (m8[mt]) {
                __nv_fp8x2_storage_t f23 = __nv_cvt_float2_to_fp8x2(
                    make_float2(s2, s3), __NV_SATFINITE, __NV_E4M3);
                *(unsigned short*)(Hout8 + (size_t)(row0 + 8) * Nc + col) = (unsigned short)f23;
            }
        }
    }

#pragma unroll
    for (int mt = 0; mt < 4; mt++) {
        float s0v = sum0[mt], s8v = sum8[mt];
        s0v += __shfl_xor_sync(0xffffffffu, s0v, 1);
        s0v += __shfl_xor_sync(0xffffffffu, s0v, 2);
        s8v += __shfl_xor_sync(0xffffffffu, s8v, 1);
        s8v += __shfl_xor_sync(0xffffffffu, s8v, 2);
        if ((lid & 3) == 0) {
            const int row0 = bm0 + warp_m * 64 + mt * 16 + rr;
            atomicAdd(&d2sq[row0], s0v);
            atomicAdd(&d2sq[row0 + 8], s8v);
        }
    }
}

// ---------------- block reduction (256 threads) ----------------
__device__ __forceinline__ float block_reduce(float v) {
    __shared__ float sh[8];
    __syncthreads();
    int lane = threadIdx.x & 31;
    int w    = threadIdx.x >> 5;
#pragma unroll
    for (int o = 16; o > 0; o >>= 1) v += __shfl_down_sync(0xffffffffu, v, o);
    if (lane == 0) sh[w] = v;
    __syncthreads();
    if (w == 0) {
        v = (lane < 8) ? sh[lane] : 0.f;
#pragma unroll
        for (int o = 4; o > 0; o >>= 1) v += __shfl_down_sync(0xffffffffu, v, o);
    }
    return v;
}

// ---------------- merged fp32 -> fp16 conversion + W row-norm fold ----------
__global__ void convert_all(const float4* __restrict__ A, uint4* __restrict__ Ah,
                            const float4* __restrict__ W1, uint4* __restrict__ W1h,
                            const float4* __restrict__ W2, uint4* __restrict__ W2h)
{
    const float4* in;
    uint4* out;
    int b = blockIdx.x;
    int which;
    if (b < 8192)      { in = A;  out = Ah;  which = 0; }
    else if (b < 9216) { in = W1; out = W1h; which = 1; b -= 8192; }
    else               { in = W2; out = W2h; which = 2; b -= 9216; }
    const int t = threadIdx.x;
    float4 v[8];
#pragma unroll
    for (int k = 0; k < 4; k++) {
        int i = b * 2048 + t * 2 + k * 512;
        v[2 * k]     = __ldcs(in + i);
        v[2 * k + 1] = __ldcs(in + i + 1);
    }
#pragma unroll
    for (int k = 0; k < 4; k++) {
        __half2 a0 = __float22half2_rn(make_float2(v[2 * k].x,     v[2 * k].y));
        __half2 a1 = __float22half2_rn(make_float2(v[2 * k].z,     v[2 * k].w));
        __half2 a2 = __float22half2_rn(make_float2(v[2 * k + 1].x, v[2 * k + 1].y));
        __half2 a3 = __float22half2_rn(make_float2(v[2 * k + 1].z, v[2 * k + 1].w));
        __stcs(out + b * 1024 + t + k * 256,
               make_uint4(*(uint32_t*)&a0, *(uint32_t*)&a1,
                          *(uint32_t*)&a2, *(uint32_t*)&a3));
    }

    if (which == 1) {
        float s = 0.f;
#pragma unroll
        for (int k = 0; k < 8; k++)
            s += v[k].x * v[k].x + v[k].y * v[k].y + v[k].z * v[k].z + v[k].w * v[k].w;
        s = block_reduce(s);
        if (t == 0) atomicAdd(&g_acc[2], sqrtf(s));
    } else if (which == 2) {
        __shared__ float srow[8];
        if (t < 8) srow[t] = 0.f;
        __syncthreads();
#pragma unroll
        for (int k = 0; k < 4; k++) {
            float p = v[2 * k].x * v[2 * k].x + v[2 * k].y * v[2 * k].y
                    + v[2 * k].z * v[2 * k].z + v[2 * k].w * v[2 * k].w
                    + v[2 * k + 1].x * v[2 * k + 1].x + v[2 * k + 1].y * v[2 * k + 1].y
                    + v[2 * k + 1].z * v[2 * k + 1].z + v[2 * k + 1].w * v[2 * k + 1].w;
#pragma unroll
            for (int o = 16; o > 0; o >>= 1) p += __shfl_xor_sync(0xffffffffu, p, o);
            if ((t & 31) == 0) atomicAdd(&srow[(t >> 7) + 2 * k], p);
        }
        __syncthreads();
        if (t < 8) atomicAdd(&g_acc[2], sqrtf(srow[t]));
    }
}

// squared distance over 8 fp16 element pairs
__device__ __forceinline__ float d2_h8(uint4 x, uint4 y) {
    float s = 0.f;
    const uint32_t* xp = (const uint32_t*)&x;
    const uint32_t* yp = (const uint32_t*)&y;
#pragma unroll
    for (int qq = 0; qq < 4; qq++) {
        float2 a = __half22float2(*(const __half2*)&xp[qq]);
        float2 b = __half22float2(*(const __half2*)&yp[qq]);
        float d0 = a.x - b.x, d1 = a.y - b.y;
        s += d0 * d0 + d1 * d1;
    }
    return s;
}

// squared distance over 16 fp8 (e4m3) element pairs
__device__ __forceinline__ float d2_f8_16(uint4 x, uint4 y) {
    float s = 0.f;
    const unsigned short* xp = (const unsigned short*)&x;
    const unsigned short* yp = (const unsigned short*)&y;
#pragma unroll
    for (int qq = 0; qq < 8; qq++) {
        __half2_raw hx = __nv_cvt_fp8x2_to_halfraw2((__nv_fp8x2_storage_t)xp[qq], __NV_E4M3);
        __half2_raw hy = __nv_cvt_fp8x2_to_halfraw2((__nv_fp8x2_storage_t)yp[qq], __NV_E4M3);
        float2 fx = __half22float2(*(const __half2*)&hx);
        float2 fy = __half22float2(*(const __half2*)&hy);
        float d0 = fx.x - fy.x, d1 = fx.y - fy.y;
        s += d0 * d0 + d1 * d1;
    }
    return s;
}

__global__ void zero_kernel() {
    int i = blockIdx.x * blockDim.x + threadIdx.x;
    if (i < NN) { g_d2sq[i] = 0.f; g_mask[i] = 0; }
    if (i == 0) { g_acc[0] = 0.f; g_acc[1] = 0.f; g_acc[2] = 0.f; }
}

// mask build + bias norms (b1: block 32, b2: block 33)
__global__ void mask_bias_kernel(const int* __restrict__ edges,
                                 const int* __restrict__ labels,
                                 const float* __restrict__ b1,
                                 const float* __restrict__ b2) {
    int b = blockIdx.x;
    if (b < 32) {
        int e = b * 256 + threadIdx.x;
        if (labels[e] != 0) {
            g_mask[edges[2 * e + 0]] = 1;
            g_mask[edges[2 * e + 1]] = 1;
        }
    } else {
        const float* p = (b == 32) ? b1 : b2;
        int len = (b == 32) ? HD : NN;
        float s = 0.f;
        for (int c = threadIdx.x; c < len; c += 256) { float x = p[c]; s += x * x; }
        s = block_reduce(s);
        if (threadIdx.x == 0) atomicAdd(&g_acc[2], sqrtf(s));
    }
}

// edge losses; H1 fp16, H2 fp8
__global__ void edge_loss_kernel(const int* __restrict__ edges,
                                 const int* __restrict__ labels) {
    int e  = blockIdx.x;
    int ni = edges[2 * e + 0];
    int nj = edges[2 * e + 1];
    int lab = labels[e];

    if (lab != 0) {
        const int t = threadIdx.x;
        const uint4* hi1 = (const uint4*)(g_H1h + (size_t)ni * HD);
        const uint4* hj1 = (const uint4*)(g_H1h + (size_t)nj * HD);
        float s1 = 0.f;
        if (t < 128) s1 = d2_h8(__ldca(hi1 + t), __ldca(hj1 + t));

        const uint4* hi2 = (const uint4*)(g_H28 + (size_t)ni * NN);
        const uint4* hj2 = (const uint4*)(g_H28 + (size_t)nj * NN);
        uint4 xi[2], xj[2];
#pragma unroll
        for (int k = 0; k < 2; k++) {
            int c = t + k * 256;
            xi[k] = __ldcs(hi2 + c);
            xj[k] = __ldcs(hj2 + c);
        }
        float s2 = d2_f8_16(xi[0], xj[0]) + d2_f8_16(xi[1], xj[1]);

        s1 = block_reduce(s1);
        s2 = block_reduce(s2);
        if (t == 0) atomicAdd(&g_acc[0], sqrtf(s1) + sqrtf(s2));
    }
    if (threadIdx.x == 0) {
        float factor = (lab != 0) ? 10.f : 1.f;
        atomicAdd(&g_acc[1], factor * (sqrtf(g_d2sq[ni]) + sqrtf(g_d2sq[nj])));
    }
}

__global__ void finalize_kernel(float* out) {
    out[0] = g_acc[0] + g_acc[1] + g_acc[2] * (float)EE;
}

// ---------------- launch ----------------
extern "C" void kernel_launch(void* const* d_in, const int* in_sizes, int n_in,
                              void* d_out, int out_size) {
    const float* A      = (const float*)d_in[0];
    const float* W1     = (const float*)d_in[1];
    const float* b1     = (const float*)d_in[2];
    const float* W2     = (const float*)d_in[3];
    const float* b2     = (const float*)d_in[4];
    const int*   edges  = (const int*)d_in[5];
    const int*   labels = (const int*)d_in[6];
    float* out = (float*)d_out;

    __half *Ah, *W1h, *W2h, *H1h;
    unsigned char *H28;
    float* d2sq;
    unsigned char* mask;
    cudaGetSymbolAddress((void**)&Ah,   g_Ah);
    cudaGetSymbolAddress((void**)&W1h,  g_W1h);
    cudaGetSymbolAddress((void**)&W2h,  g_W2h);
    cudaGetSymbolAddress((void**)&H1h,  g_H1h);
    cudaGetSymbolAddress((void**)&H28,  g_H28);
    cudaGetSymbolAddress((void**)&d2sq, g_d2sq);
    cudaGetSymbolAddress((void**)&mask, g_mask);

    cudaFuncSetAttribute(gemm1_hmma,
                         cudaFuncAttributeMaxDynamicSharedMemorySize, G_SMEM);
    cudaFuncSetAttribute(gemm2_fused,
                         cudaFuncAttributeMaxDynamicSharedMemorySize, G_SMEM);

    zero_kernel<<<NN / 256, 256>>>();
    mask_bias_kernel<<<34, 256>>>(edges, labels, b1, b2);

    // merged fp32 -> fp16 conversions (+ W row-norm fold)
    convert_all<<<10240, 256>>>((const float4*)A,  (uint4*)Ah,
                                (const float4*)W1, (uint4*)W1h,
                                (const float4*)W2, (uint4*)W2h);

    // H1 = sigmoid(A @ W1^T + b1): M=8192, Nc=1024, K=8192
    gemm1_hmma<<<dim3(HD / 128, NN / 128), 256, G_SMEM>>>(Ah, W1h, b1, H1h, NN, HD);
    // H2 = sigmoid(H1 @ W2^T + b2) + fused residual, mask-gated fp8 stores
    gemm2_fused<<<dim3(NN / 128, NN / 128), 256, G_SMEM>>>(
        H1h, W2h, b2, H28, Ah, d2sq, mask, HD, NN);

    edge_loss_kernel<<<EE, 256>>>(edges, labels);
    finalize_kernel<<<1, 1>>>(out);
}